// round 7
// baseline (speedup 1.0000x reference)
#include <cuda_runtime.h>

// ---------------------------------------------------------------------------
// SlotAttention fused. B=32, N=16384, S=8, D=64, H=128, ITERS=3.
// k_pass: per-warp full-prefetch (2 x 32-row tiles staged in prologue via
//         cp.async), folded-LN logits + softmax + rank-1 accum, f32x2 FMAs,
//         no block syncs and no mid-loop staging in the mainloop.
// k_update/k_init: one block per (batch, slot). Fixed-order reductions.
// ---------------------------------------------------------------------------

#define BB 32
#define NN 16384
#define SS 8
#define DD 64
#define HH 128
#define NBLKX 64                 // pass blocks per batch (256 rows each)
#define WTILES 2                 // warp-tiles per warp (32 rows each)
#define PREC 528                 // floats per record: 512 Pacc + 8 Sg + 8 Sb
#define PASS_THREADS 128
// smem: xs 4096*16 + as4 256*16 + wts 128*16 + tail 80*4 = 72000 -> pad 72064
#define SMEM_BYTES 72064

typedef unsigned long long ull;

__device__ float  g_slots[BB * SS * DD];
__device__ float4 g_wts4[BB * 128];          // [b][k=0..15][s=0..7]
__device__ float  g_c0[BB][SS];
__device__ float  g_c1[BB][SS];
__device__ float4 g_part4[(size_t)BB * NBLKX * 132];

#define F2FMA(d, a, b) asm("fma.rn.f32x2 %0, %1, %2, %0;" : "+l"(d) : "l"(a), "l"(b))
#define F2ADD(d, a, b) asm("add.rn.f32x2 %0, %1, %2;" : "=l"(d) : "l"(a), "l"(b))
#define F2PACK(v, lo, hi) asm("mov.b64 %0, {%1, %2};" : "=l"(v) : "f"(lo), "f"(hi))
#define F2UNPK(lo, hi, v) asm("mov.b64 {%0, %1}, %2;" : "=f"(lo), "=f"(hi) : "l"(v))

__device__ __forceinline__ float sigm(float x) { return 1.f / (1.f + __expf(-x)); }

__device__ __forceinline__ float dot16x4(const float4* a, const float4* w, float acc) {
#pragma unroll
    for (int e = 0; e < 16; ++e) {
        float4 av = a[e], wv = w[e];
        acc = fmaf(av.x, wv.x, fmaf(av.y, wv.y, fmaf(av.z, wv.z, fmaf(av.w, wv.w, acc))));
    }
    return acc;
}
__device__ __forceinline__ float dot8x4(const float4* a, const float4* w) {
    float acc = 0.f;
#pragma unroll
    for (int e = 0; e < 8; ++e) {
        float4 av = a[e], wv = w[e];
        acc = fmaf(av.x, wv.x, fmaf(av.y, wv.y, fmaf(av.z, wv.z, fmaf(av.w, wv.w, acc))));
    }
    return acc;
}

__device__ __forceinline__ void ln64_warp(const float* in, float* out,
                                          const float* __restrict__ g,
                                          const float* __restrict__ bt, int t) {
    if (t < 32) {
        float v0 = in[t], v1 = in[t + 32];
        float sum = v0 + v1;
        float sq  = fmaf(v0, v0, v1 * v1);
#pragma unroll
        for (int off = 16; off; off >>= 1) {
            sum += __shfl_xor_sync(0xffffffffu, sum, off);
            sq  += __shfl_xor_sync(0xffffffffu, sq,  off);
        }
        float m    = sum * (1.f / 64.f);
        float istd = rsqrtf(fmaf(sq, 1.f / 64.f, -m * m) + 1e-5f);
        out[t]      = fmaf((v0 - m) * istd, g[t],      bt[t]);
        out[t + 32] = fmaf((v1 - m) * istd, g[t + 32], bt[t + 32]);
    }
}

// ---------------------------------------------------------------------------
__device__ __forceinline__ void prep_slot(
    int b, int s, int t,
    const float* snew, float* lns, float* qv, float* qtv, float* hpart,
    const float* __restrict__ lnsg, const float* __restrict__ lnsb,
    const float* __restrict__ Wq,   const float* __restrict__ Wk,
    const float* __restrict__ lng,  const float* __restrict__ lnb)
{
    ln64_warp(snew, lns, lnsg, lnsb, t);
    __syncthreads();
    {
        int dd = t & 63, h = t >> 6;
        const float4* wr = (const float4*)(Wq + dd * 64) + h * 8;
        const float4* lv = (const float4*)lns + h * 8;
        hpart[t] = dot8x4(lv, wr);
    }
    __syncthreads();
    if (t < 64) qv[t] = (hpart[t] + hpart[t + 64]) * 0.125f;
    __syncthreads();
    {
        int e = t & 63, h = t >> 6;
        float acc = 0.f;
        const float* wk = Wk + (h * 32) * 64 + e;
#pragma unroll 8
        for (int dd = 0; dd < 32; ++dd) acc = fmaf(qv[h * 32 + dd], wk[dd * 64], acc);
        hpart[t] = acc;
    }
    __syncthreads();
    if (t < 64) qtv[t] = hpart[t] + hpart[t + 64];
    __syncthreads();
    if (t < 64) {
        int k = t >> 2, j = t & 3;
        reinterpret_cast<float*>(g_wts4 + b * 128)[(k * 8 + s) * 4 + j] = lng[t] * qtv[t];
    }
    if (t < 32) {
        float p1 = fmaf(lng[t + 32], qtv[t + 32], lng[t] * qtv[t]);
        float p0 = fmaf(lnb[t + 32], qtv[t + 32], lnb[t] * qtv[t]);
#pragma unroll
        for (int off = 16; off; off >>= 1) {
            p1 += __shfl_xor_sync(0xffffffffu, p1, off);
            p0 += __shfl_xor_sync(0xffffffffu, p0, off);
        }
        if (t == 0) { g_c1[b][s] = p1; g_c0[b][s] = p0; }
    }
}

// ---------------------------------------------------------------------------
__global__ void __launch_bounds__(128) k_init(
    const float* __restrict__ noise, const float* __restrict__ mu,
    const float* __restrict__ lsig,
    const float* __restrict__ lnsg, const float* __restrict__ lnsb,
    const float* __restrict__ Wq,   const float* __restrict__ Wk,
    const float* __restrict__ lng,  const float* __restrict__ lnb)
{
    __shared__ __align__(16) float snew[64], lns[64], qv[64], qtv[64], hpart[128];
    int bs = blockIdx.x, b = bs >> 3, s = bs & 7, t = threadIdx.x;
    if (t < 64) {
        int idx = s * 64 + t;
        float v = fmaf(__expf(lsig[idx]), noise[b * 512 + idx], mu[idx]);
        snew[t] = v;
        g_slots[b * 512 + idx] = v;
    }
    __syncthreads();
    prep_slot(b, s, t, snew, lns, qv, qtv, hpart, lnsg, lnsb, Wq, Wk, lng, lnb);
}

// ---------------------------------------------------------------------------
// stage one 32-row warp-tile (8KB) via cp.async (lane l issues 16 x 16B)
// ---------------------------------------------------------------------------
__device__ __forceinline__ void stage_tile(const float4* __restrict__ gsrc,
                                           unsigned sdst, int l)
{
#pragma unroll
    for (int j = 0; j < 16; ++j) {
        int flat = j * 32 + l;
        int row = flat >> 4, k = flat & 15;
        unsigned dst = sdst + (unsigned)((row * 16 + (k ^ (row & 15))) * 16);
        asm volatile("cp.async.cg.shared.global [%0], [%1], 16;"
                     :: "r"(dst), "l"(gsrc + flat));
    }
    asm volatile("cp.async.commit_group;");
}

// ---------------------------------------------------------------------------
// the big fused pass. dynamic smem layout (float4 units):
//   [0,4096)    xs   : 4 warps x 2 buf x 512 (64KB)
//   [4096,4352) as4  : 4 warps x 64 (4KB)
//   [4352,4480) wts  : 128 (2KB)
//   tail floats: c0s[8], c1s[8], redSg[4][8], redSb[4][8]
// ---------------------------------------------------------------------------
__global__ void __launch_bounds__(PASS_THREADS) k_pass(const float4* __restrict__ x4)
{
    extern __shared__ __align__(16) float4 smem[];
    float4* xs   = smem;
    float4* as4  = smem + 4096;
    float4* wts  = smem + 4352;
    float*  tail = (float*)(smem + 4480);   // 80 floats

    const int b = blockIdx.y;
    const int t = threadIdx.x;
    const int w = t >> 5, l = t & 31;

    unsigned smem_u32;
    { size_t a = __cvta_generic_to_shared(xs); smem_u32 = (unsigned)a; }
    const unsigned xs_base = smem_u32 + (unsigned)(w * 1024 * 16);

    // prologue: prefetch BOTH warp-tiles (no mid-loop staging)
    const float4* gwarp = x4 + ((size_t)b * NN + (size_t)blockIdx.x * 256 + w * 64) * 16;
    stage_tile(gwarp,       xs_base,        l);
    stage_tile(gwarp + 512, xs_base + 8192, l);

    wts[t] = g_wts4[b * 128 + t];
    if (t < 8)  tail[t]     = g_c0[b][t];
    if (t >= 8 && t < 16) tail[t] = g_c1[b][t - 8];
    __syncthreads();

    float c0r[8], c1r[8], gacc[8], bacc[8];
    ull p2[8];
#pragma unroll
    for (int s = 0; s < 8; ++s) {
        c0r[s] = tail[s]; c1r[s] = tail[8 + s];
        gacc[s] = 0.f; bacc[s] = 0.f; p2[s] = 0ULL;
    }

    const ulonglong2* wt2 = reinterpret_cast<const ulonglong2*>(wts);
    float4* as4w = as4 + w * 64;
    const int g2 = l >> 4, e4 = l & 15;

#pragma unroll
    for (int tl = 0; tl < WTILES; ++tl) {
        if (tl == 0) asm volatile("cp.async.wait_group 1;" ::: "memory");
        else         asm volatile("cp.async.wait_group 0;" ::: "memory");
        __syncwarp();

        const ulonglong2* xs2w = reinterpret_cast<const ulonglong2*>(
            xs + w * 1024 + tl * 512);

        // ---- phase 1: lane l owns row l of this 32-row tile ----
        {
            ull d2[8];
#pragma unroll
            for (int s = 0; s < 8; ++s) d2[s] = 0ULL;
            ull sum2 = 0ULL, sqa = 0ULL, sqb = 0ULL;
            const int rb = l * 16, ro = l & 15;
#pragma unroll
            for (int k = 0; k < 16; ++k) {
                ulonglong2 v = xs2w[rb + (k ^ ro)];
                ull tv; F2ADD(tv, v.x, v.y); F2ADD(sum2, sum2, tv);
                F2FMA(sqa, v.x, v.x);
                F2FMA(sqb, v.y, v.y);
#pragma unroll
                for (int s = 0; s < 8; ++s) {
                    ulonglong2 wv = wt2[k * 8 + s];
                    F2FMA(d2[s], v.x, wv.x);
                    F2FMA(d2[s], v.y, wv.y);
                }
            }
            float slo, shi; F2UNPK(slo, shi, sum2);
            float sum = slo + shi;
            float qa0, qa1, qb0, qb1;
            F2UNPK(qa0, qa1, sqa); F2UNPK(qb0, qb1, sqb);
            float sq = (qa0 + qa1) + (qb0 + qb1);
            float m    = sum * (1.f / 64.f);
            float istd = rsqrtf(fmaf(sq, 1.f / 64.f, -m * m) + 1e-5f);
            float lo[8], mx = -3.4e38f;
#pragma unroll
            for (int s = 0; s < 8; ++s) {
                float dlo, dhi; F2UNPK(dlo, dhi, d2[s]);
                float d = dlo + dhi;
                lo[s] = fmaf(istd, fmaf(-m, c1r[s], d), c0r[s]);
                mx = fmaxf(mx, lo[s]);
            }
            float pr[8], ps = 0.f;
#pragma unroll
            for (int s = 0; s < 8; ++s) { pr[s] = __expf(lo[s] - mx); ps += pr[s]; }
            float rc  = 1.f / ps;
            float tmi = m * istd;
            float al[8];
#pragma unroll
            for (int s = 0; s < 8; ++s) {
                float a = fmaf(pr[s], rc, 1e-8f);   // softmax + EPS
                gacc[s] += a;
                bacc[s] = fmaf(a, tmi, bacc[s]);
                al[s]   = a * istd;
            }
            as4w[l * 2 + 0] = make_float4(al[0], al[1], al[2], al[3]);
            as4w[l * 2 + 1] = make_float4(al[4], al[5], al[6], al[7]);
        }
        __syncwarp();

        // ---- phase 2: lane (g2, e4) owns slots 4g2..4g2+3 x elems 4e4..4e4+3 ----
#pragma unroll 4
        for (int r = 0; r < 32; ++r) {
            float4 av = as4w[r * 2 + g2];
            ulonglong2 xq = xs2w[r * 16 + (e4 ^ (r & 15))];
            ull a0, a1, a2, a3;
            F2PACK(a0, av.x, av.x); F2PACK(a1, av.y, av.y);
            F2PACK(a2, av.z, av.z); F2PACK(a3, av.w, av.w);
            F2FMA(p2[0], xq.x, a0); F2FMA(p2[1], xq.y, a0);
            F2FMA(p2[2], xq.x, a1); F2FMA(p2[3], xq.y, a1);
            F2FMA(p2[4], xq.x, a2); F2FMA(p2[5], xq.y, a2);
            F2FMA(p2[6], xq.x, a3); F2FMA(p2[7], xq.y, a3);
        }
        __syncwarp();
    }

    // ---- Sg/Sb warp reduce ----
#pragma unroll
    for (int s = 0; s < 8; ++s) {
        float gv = gacc[s], bv = bacc[s];
#pragma unroll
        for (int off = 16; off; off >>= 1) {
            gv += __shfl_xor_sync(0xffffffffu, gv, off);
            bv += __shfl_xor_sync(0xffffffffu, bv, off);
        }
        if (l == 0) { tail[16 + w * 8 + s] = gv; tail[48 + w * 8 + s] = bv; }
    }
    __syncthreads();   // all warps done; xs reusable as reduction scratch

    // ---- cross-warp Pacc reduce (fixed order) ----
    float4* red4 = xs;   // [w][128] float4 = [w][s*16+e4]
#pragma unroll
    for (int ss = 0; ss < 4; ++ss) {
        float x0, x1, x2, x3;
        F2UNPK(x0, x1, p2[2 * ss]);
        F2UNPK(x2, x3, p2[2 * ss + 1]);
        red4[w * 128 + (4 * g2 + ss) * 16 + e4] = make_float4(x0, x1, x2, x3);
    }
    __syncthreads();

    float4* gp4 = g_part4 + ((size_t)(b * NBLKX + blockIdx.x)) * 132;
    {
        float4 a = red4[t], bb2 = red4[128 + t], c = red4[256 + t], d = red4[384 + t];
        float4 o;
        o.x = ((a.x + bb2.x) + c.x) + d.x;
        o.y = ((a.y + bb2.y) + c.y) + d.y;
        o.z = ((a.z + bb2.z) + c.z) + d.z;
        o.w = ((a.w + bb2.w) + c.w) + d.w;
        gp4[t] = o;
    }
    if (t < 16) {
        const float* src = tail + 16 + (t >= 8 ? 32 : 0) + (t & 7);
        float v = ((src[0] + src[8]) + src[16]) + src[24];
        reinterpret_cast<float*>(gp4)[512 + (t >= 8 ? 8 : 0) + (t & 7)] = v;
    }
}

// ---------------------------------------------------------------------------
// slot update: one block per (b,s)
// ---------------------------------------------------------------------------
__global__ void __launch_bounds__(128) k_update(
    const float* __restrict__ lng,  const float* __restrict__ lnb,
    const float* __restrict__ lnsg, const float* __restrict__ lnsb,
    const float* __restrict__ lnmg, const float* __restrict__ lnmb,
    const float* __restrict__ Wq,   const float* __restrict__ Wk,
    const float* __restrict__ Wv,
    const float* __restrict__ W_ih, const float* __restrict__ W_hh,
    const float* __restrict__ b_ih, const float* __restrict__ b_hh,
    const float* __restrict__ W1,   const float* __restrict__ b1,
    const float* __restrict__ W2,   const float* __restrict__ b2,
    float* __restrict__ out, int last)
{
    __shared__ __align__(16) float P[64], Uv[64], upds[64], slp[64];
    __shared__ __align__(16) float gi[192], gh[192], updh[64], mln[64];
    __shared__ __align__(16) float hhs[128], snew[64];
    __shared__ __align__(16) float lns[64], qv[64], qtv[64], hpart[128];
    __shared__ float sred[4];
    __shared__ float sSg, sSb;

    int bs = blockIdx.x, b = bs >> 3, s = bs & 7, t = threadIdx.x;

    const float* pb = reinterpret_cast<const float*>(g_part4) + (size_t)b * NBLKX * PREC;
    {
        int e = t & 63, h = t >> 6;
        const float* src = pb + (size_t)h * 32 * PREC + s * 64 + e;
        float acc = 0.f;
#pragma unroll 8
        for (int blk = 0; blk < 32; ++blk) acc += src[(size_t)blk * PREC];
        hpart[t] = acc;
    }
    if (t < 4) {
        int which = t & 1, h = t >> 1;
        const float* src = pb + (size_t)h * 32 * PREC + 512 + which * 8 + s;
        float acc = 0.f;
#pragma unroll 8
        for (int blk = 0; blk < 32; ++blk) acc += src[(size_t)blk * PREC];
        sred[t] = acc;
    }
    if (t < 64) slp[t] = g_slots[b * 512 + s * 64 + t];
    __syncthreads();
    if (t < 64) P[t] = hpart[t] + hpart[t + 64];
    if (t == 0) { sSg = sred[0] + sred[2]; sSb = sred[1] + sred[3]; }
    __syncthreads();

    if (t < 64) Uv[t] = fmaf(lng[t], P[t] - sSb, lnb[t] * sSg) / sSg;
    __syncthreads();

    {
        int dd = t & 63, h = t >> 6;
        const float4* wr = (const float4*)(Wv + dd * 64) + h * 8;
        const float4* uv = (const float4*)Uv + h * 8;
        float r = dot8x4(uv, wr);
        __syncthreads();
        hpart[t] = r;
    }
    __syncthreads();
    if (t < 64) upds[t] = hpart[t] + hpart[t + 64];
    __syncthreads();

#pragma unroll
    for (int k = 0; k < 3; ++k) {
        int id = t + 128 * k;
        if (id < 192) {
            int j = id;
            gi[j] = dot16x4((const float4*)upds, (const float4*)(W_ih + j * 64), b_ih[j]);
        } else {
            int j = id - 192;
            gh[j] = dot16x4((const float4*)slp, (const float4*)(W_hh + j * 64), b_hh[j]);
        }
    }
    __syncthreads();

    if (t < 64) {
        float r = sigm(gi[t]      + gh[t]);
        float z = sigm(gi[64 + t] + gh[64 + t]);
        float n = tanhf(fmaf(r, gh[128 + t], gi[128 + t]));
        updh[t] = fmaf(z, slp[t] - n, n);
    }
    __syncthreads();

    ln64_warp(updh, mln, lnmg, lnmb, t);
    __syncthreads();

    hhs[t] = fmaxf(dot16x4((const float4*)mln, (const float4*)(W1 + t * 64), b1[t]), 0.f);
    __syncthreads();

    {
        int dd = t & 63, h = t >> 6;
        const float4* wr = (const float4*)(W2 + dd * 128) + h * 16;
        const float4* hv = (const float4*)hhs + h * 16;
        hpart[t] = dot16x4(hv, wr, 0.f);
    }
    __syncthreads();
    if (t < 64) {
        float v = updh[t] + b2[t] + (hpart[t] + hpart[t + 64]);
        snew[t] = v;
        g_slots[b * 512 + s * 64 + t] = v;
        if (last) out[b * 512 + s * 64 + t] = v;
    }
    __syncthreads();

    if (!last)
        prep_slot(b, s, t, snew, lns, qv, qtv, hpart, lnsg, lnsb, Wq, Wk, lng, lnb);
}

// ---------------------------------------------------------------------------
extern "C" void kernel_launch(void* const* d_in, const int* in_sizes, int n_in,
                              void* d_out, int out_size)
{
    const float* x     = (const float*)d_in[0];
    const float* noise = (const float*)d_in[1];
    const float* mu    = (const float*)d_in[2];
    const float* lsig  = (const float*)d_in[3];
    const float* lng   = (const float*)d_in[4];
    const float* lnb   = (const float*)d_in[5];
    const float* lnsg  = (const float*)d_in[6];
    const float* lnsb  = (const float*)d_in[7];
    const float* lnmg  = (const float*)d_in[8];
    const float* lnmb  = (const float*)d_in[9];
    const float* Wq    = (const float*)d_in[10];
    const float* Wk    = (const float*)d_in[11];
    const float* Wv    = (const float*)d_in[12];
    const float* W_ih  = (const float*)d_in[13];
    const float* W_hh  = (const float*)d_in[14];
    const float* b_ih  = (const float*)d_in[15];
    const float* b_hh  = (const float*)d_in[16];
    const float* W1    = (const float*)d_in[17];
    const float* b1    = (const float*)d_in[18];
    const float* W2    = (const float*)d_in[19];
    const float* b2    = (const float*)d_in[20];
    float* out = (float*)d_out;

    cudaFuncSetAttribute(k_pass, cudaFuncAttributeMaxDynamicSharedMemorySize, SMEM_BYTES);

    k_init<<<BB * SS, 128>>>(noise, mu, lsig, lnsg, lnsb, Wq, Wk, lng, lnb);

    for (int it = 0; it < 3; ++it) {
        k_pass<<<dim3(NBLKX, BB), PASS_THREADS, SMEM_BYTES>>>((const float4*)x);
        k_update<<<BB * SS, 128>>>(lng, lnb, lnsg, lnsb, lnmg, lnmb,
                                   Wq, Wk, Wv, W_ih, W_hh, b_ih, b_hh,
                                   W1, b1, W2, b2, out, it == 2);
    }
}

// round 8
// speedup vs baseline: 1.0091x; 1.0091x over previous
#include <cuda_runtime.h>

// ---------------------------------------------------------------------------
// SlotAttention fused. B=32, N=16384, S=8, D=64, H=128, ITERS=3.
// k_pass: per-warp cp.async pipelined 16-row tiles (ring-2), phase-1 k-split
//         across lane halves (shfl-combined), folded-LN logits + softmax +
//         rank-1 accum, f32x2 FMAs. No block syncs in mainloop. 37KB smem
//         -> 5 CTAs/SM target.
// k_update/k_init: one block per (batch, slot). Fixed-order reductions.
// ---------------------------------------------------------------------------

#define BB 32
#define NN 16384
#define SS 8
#define DD 64
#define HH 128
#define NBLKX 32                 // pass blocks per batch (512 rows each)
#define NTILES 8                 // 16-row tiles per warp (128 rows/warp)
#define PREC 528                 // floats per record: 512 Pacc + 8 Sg + 8 Sb
#define PASS_THREADS 128
// smem: xs 2048*16 + as4 128*16 + wts 128*16 + tail 80*4 = 37184 bytes
#define SMEM_BYTES 37184

typedef unsigned long long ull;

__device__ float  g_slots[BB * SS * DD];
__device__ float4 g_wts4[BB * 128];          // [b][k=0..15][s=0..7]
__device__ float  g_c0[BB][SS];
__device__ float  g_c1[BB][SS];
__device__ float4 g_part4[(size_t)BB * NBLKX * 132];

#define F2FMA(d, a, b) asm("fma.rn.f32x2 %0, %1, %2, %0;" : "+l"(d) : "l"(a), "l"(b))
#define F2ADD(d, a, b) asm("add.rn.f32x2 %0, %1, %2;" : "=l"(d) : "l"(a), "l"(b))
#define F2PACK(v, lo, hi) asm("mov.b64 %0, {%1, %2};" : "=l"(v) : "f"(lo), "f"(hi))
#define F2UNPK(lo, hi, v) asm("mov.b64 {%0, %1}, %2;" : "=f"(lo), "=f"(hi) : "l"(v))

__device__ __forceinline__ float sigm(float x) { return 1.f / (1.f + __expf(-x)); }

__device__ __forceinline__ float dot16x4(const float4* a, const float4* w, float acc) {
#pragma unroll
    for (int e = 0; e < 16; ++e) {
        float4 av = a[e], wv = w[e];
        acc = fmaf(av.x, wv.x, fmaf(av.y, wv.y, fmaf(av.z, wv.z, fmaf(av.w, wv.w, acc))));
    }
    return acc;
}
__device__ __forceinline__ float dot8x4(const float4* a, const float4* w) {
    float acc = 0.f;
#pragma unroll
    for (int e = 0; e < 8; ++e) {
        float4 av = a[e], wv = w[e];
        acc = fmaf(av.x, wv.x, fmaf(av.y, wv.y, fmaf(av.z, wv.z, fmaf(av.w, wv.w, acc))));
    }
    return acc;
}

__device__ __forceinline__ void ln64_warp(const float* in, float* out,
                                          const float* __restrict__ g,
                                          const float* __restrict__ bt, int t) {
    if (t < 32) {
        float v0 = in[t], v1 = in[t + 32];
        float sum = v0 + v1;
        float sq  = fmaf(v0, v0, v1 * v1);
#pragma unroll
        for (int off = 16; off; off >>= 1) {
            sum += __shfl_xor_sync(0xffffffffu, sum, off);
            sq  += __shfl_xor_sync(0xffffffffu, sq,  off);
        }
        float m    = sum * (1.f / 64.f);
        float istd = rsqrtf(fmaf(sq, 1.f / 64.f, -m * m) + 1e-5f);
        out[t]      = fmaf((v0 - m) * istd, g[t],      bt[t]);
        out[t + 32] = fmaf((v1 - m) * istd, g[t + 32], bt[t + 32]);
    }
}

// ---------------------------------------------------------------------------
__device__ __forceinline__ void prep_slot(
    int b, int s, int t,
    const float* snew, float* lns, float* qv, float* qtv, float* hpart,
    const float* __restrict__ lnsg, const float* __restrict__ lnsb,
    const float* __restrict__ Wq,   const float* __restrict__ Wk,
    const float* __restrict__ lng,  const float* __restrict__ lnb)
{
    ln64_warp(snew, lns, lnsg, lnsb, t);
    __syncthreads();
    {
        int dd = t & 63, h = t >> 6;
        const float4* wr = (const float4*)(Wq + dd * 64) + h * 8;
        const float4* lv = (const float4*)lns + h * 8;
        hpart[t] = dot8x4(lv, wr);
    }
    __syncthreads();
    if (t < 64) qv[t] = (hpart[t] + hpart[t + 64]) * 0.125f;
    __syncthreads();
    {
        int e = t & 63, h = t >> 6;
        float acc = 0.f;
        const float* wk = Wk + (h * 32) * 64 + e;
#pragma unroll 8
        for (int dd = 0; dd < 32; ++dd) acc = fmaf(qv[h * 32 + dd], wk[dd * 64], acc);
        hpart[t] = acc;
    }
    __syncthreads();
    if (t < 64) qtv[t] = hpart[t] + hpart[t + 64];
    __syncthreads();
    if (t < 64) {
        int k = t >> 2, j = t & 3;
        reinterpret_cast<float*>(g_wts4 + b * 128)[(k * 8 + s) * 4 + j] = lng[t] * qtv[t];
    }
    if (t < 32) {
        float p1 = fmaf(lng[t + 32], qtv[t + 32], lng[t] * qtv[t]);
        float p0 = fmaf(lnb[t + 32], qtv[t + 32], lnb[t] * qtv[t]);
#pragma unroll
        for (int off = 16; off; off >>= 1) {
            p1 += __shfl_xor_sync(0xffffffffu, p1, off);
            p0 += __shfl_xor_sync(0xffffffffu, p0, off);
        }
        if (t == 0) { g_c1[b][s] = p1; g_c0[b][s] = p0; }
    }
}

// ---------------------------------------------------------------------------
__global__ void __launch_bounds__(128) k_init(
    const float* __restrict__ noise, const float* __restrict__ mu,
    const float* __restrict__ lsig,
    const float* __restrict__ lnsg, const float* __restrict__ lnsb,
    const float* __restrict__ Wq,   const float* __restrict__ Wk,
    const float* __restrict__ lng,  const float* __restrict__ lnb)
{
    __shared__ __align__(16) float snew[64], lns[64], qv[64], qtv[64], hpart[128];
    int bs = blockIdx.x, b = bs >> 3, s = bs & 7, t = threadIdx.x;
    if (t < 64) {
        int idx = s * 64 + t;
        float v = fmaf(__expf(lsig[idx]), noise[b * 512 + idx], mu[idx]);
        snew[t] = v;
        g_slots[b * 512 + idx] = v;
    }
    __syncthreads();
    prep_slot(b, s, t, snew, lns, qv, qtv, hpart, lnsg, lnsb, Wq, Wk, lng, lnb);
}

// ---------------------------------------------------------------------------
// stage one 16-row warp-tile (4KB) via cp.async (lane l issues 8 x 16B)
// ---------------------------------------------------------------------------
__device__ __forceinline__ void stage_tile16(const float4* __restrict__ gsrc,
                                             unsigned sdst, int l)
{
#pragma unroll
    for (int j = 0; j < 8; ++j) {
        int flat = j * 32 + l;
        int row = flat >> 4, k = flat & 15;
        unsigned dst = sdst + (unsigned)((row * 16 + (k ^ row)) * 16);
        asm volatile("cp.async.cg.shared.global [%0], [%1], 16;"
                     :: "r"(dst), "l"(gsrc + flat));
    }
    asm volatile("cp.async.commit_group;");
}

// ---------------------------------------------------------------------------
// the big fused pass. dynamic smem layout (float4 units):
//   [0,2048)    xs   : 4 warps x 2 ring x 256 (32KB)
//   [2048,2176) as4  : 4 warps x 32 (2KB)
//   [2176,2304) wts  : 128 (2KB)
//   tail floats: c0s[8], c1s[8], redSg[4][8], redSb[4][8]
// ---------------------------------------------------------------------------
__global__ void __launch_bounds__(PASS_THREADS, 5) k_pass(const float4* __restrict__ x4)
{
    extern __shared__ __align__(16) float4 smem[];
    float4* xs   = smem;
    float4* as4  = smem + 2048;
    float4* wts  = smem + 2176;
    float*  tail = (float*)(smem + 2304);   // 80 floats

    const int b = blockIdx.y;
    const int t = threadIdx.x;
    const int w = t >> 5, l = t & 31;

    unsigned smem_u32;
    { size_t a = __cvta_generic_to_shared(xs); smem_u32 = (unsigned)a; }
    const unsigned xs_base = smem_u32 + (unsigned)(w * 512 * 16);

    // prologue: prefetch tiles 0 and 1 (ring-2; mid-loop staging resumes below)
    const float4* gwarp = x4 + ((size_t)b * NN + (size_t)blockIdx.x * 512 + w * 128) * 16;
    stage_tile16(gwarp,       xs_base,        l);
    stage_tile16(gwarp + 256, xs_base + 4096, l);

    wts[t] = g_wts4[b * 128 + t];
    if (t < 8)  tail[t]     = g_c0[b][t];
    if (t >= 8 && t < 16) tail[t] = g_c1[b][t - 8];
    __syncthreads();

    float c0r[8], c1r[8], gacc[8], bacc[8];
    ull p2[8];
#pragma unroll
    for (int s = 0; s < 8; ++s) {
        c0r[s] = tail[s]; c1r[s] = tail[8 + s];
        gacc[s] = 0.f; bacc[s] = 0.f; p2[s] = 0ULL;
    }

    const ulonglong2* wt2 = reinterpret_cast<const ulonglong2*>(wts);
    float4* as4w = as4 + w * 32;
    const int r  = l & 15;       // phase-1 row owned (both lane halves)
    const int kh = l >> 4;       // phase-1 k-half
    const int g2 = l >> 4;       // phase-2 slot group
    const int e4 = l & 15;       // phase-2 element quad

#pragma unroll
    for (int tl = 0; tl < NTILES; ++tl) {
        if (tl < NTILES - 1) asm volatile("cp.async.wait_group 1;" ::: "memory");
        else                 asm volatile("cp.async.wait_group 0;" ::: "memory");
        __syncwarp();

        const ulonglong2* xs2w = reinterpret_cast<const ulonglong2*>(
            xs + w * 512 + (tl & 1) * 256);

        // ---- phase 1: lanes l and l+16 share row r, split k 8/8 ----
        {
            ull d2[8];
#pragma unroll
            for (int s = 0; s < 8; ++s) d2[s] = 0ULL;
            ull sum2 = 0ULL, sqa = 0ULL, sqb = 0ULL;
#pragma unroll
            for (int j = 0; j < 8; ++j) {
                int k = kh * 8 + j;
                ulonglong2 v = xs2w[r * 16 + (k ^ r)];
                ull tv; F2ADD(tv, v.x, v.y); F2ADD(sum2, sum2, tv);
                F2FMA(sqa, v.x, v.x);
                F2FMA(sqb, v.y, v.y);
#pragma unroll
                for (int s = 0; s < 8; ++s) {
                    ulonglong2 wv = wt2[k * 8 + s];
                    F2FMA(d2[s], v.x, wv.x);
                    F2FMA(d2[s], v.y, wv.y);
                }
            }
            // combine lane halves (commutative adds -> both halves identical)
#pragma unroll
            for (int s = 0; s < 8; ++s) {
                ull o = __shfl_xor_sync(0xffffffffu, d2[s], 16);
                F2ADD(d2[s], d2[s], o);
            }
            { ull o = __shfl_xor_sync(0xffffffffu, sum2, 16); F2ADD(sum2, sum2, o); }
            { ull o = __shfl_xor_sync(0xffffffffu, sqa,  16); F2ADD(sqa,  sqa,  o); }
            { ull o = __shfl_xor_sync(0xffffffffu, sqb,  16); F2ADD(sqb,  sqb,  o); }

            float slo, shi; F2UNPK(slo, shi, sum2);
            float sum = slo + shi;
            float qa0, qa1, qb0, qb1;
            F2UNPK(qa0, qa1, sqa); F2UNPK(qb0, qb1, sqb);
            float sq = (qa0 + qa1) + (qb0 + qb1);
            float m    = sum * (1.f / 64.f);
            float istd = rsqrtf(fmaf(sq, 1.f / 64.f, -m * m) + 1e-5f);
            float lo[8], mx = -3.4e38f;
#pragma unroll
            for (int s = 0; s < 8; ++s) {
                float dlo, dhi; F2UNPK(dlo, dhi, d2[s]);
                float d = dlo + dhi;
                lo[s] = fmaf(istd, fmaf(-m, c1r[s], d), c0r[s]);
                mx = fmaxf(mx, lo[s]);
            }
            float pr[8], ps = 0.f;
#pragma unroll
            for (int s = 0; s < 8; ++s) { pr[s] = __expf(lo[s] - mx); ps += pr[s]; }
            float rc  = 1.f / ps;
            float tmi = m * istd;
            float al[8];
#pragma unroll
            for (int s = 0; s < 8; ++s) {
                float a = fmaf(pr[s], rc, 1e-8f);   // softmax + EPS
                gacc[s] += a;                        // duplicated x2 -> scaled 0.5 later
                bacc[s] = fmaf(a, tmi, bacc[s]);
                al[s]   = a * istd;
            }
            if (kh == 0) {
                as4w[r * 2 + 0] = make_float4(al[0], al[1], al[2], al[3]);
                as4w[r * 2 + 1] = make_float4(al[4], al[5], al[6], al[7]);
            }
        }
        __syncwarp();

        // ---- phase 2: lane (g2, e4) owns slots 4g2..4g2+3 x elems 4e4..4e4+3 ----
#pragma unroll 4
        for (int rr = 0; rr < 16; ++rr) {
            float4 av = as4w[rr * 2 + g2];
            ulonglong2 xq = xs2w[rr * 16 + (e4 ^ rr)];
            ull a0, a1, a2, a3;
            F2PACK(a0, av.x, av.x); F2PACK(a1, av.y, av.y);
            F2PACK(a2, av.z, av.z); F2PACK(a3, av.w, av.w);
            F2FMA(p2[0], xq.x, a0); F2FMA(p2[1], xq.y, a0);
            F2FMA(p2[2], xq.x, a1); F2FMA(p2[3], xq.y, a1);
            F2FMA(p2[4], xq.x, a2); F2FMA(p2[5], xq.y, a2);
            F2FMA(p2[6], xq.x, a3); F2FMA(p2[7], xq.y, a3);
        }
        __syncwarp();

        if (tl < NTILES - 2)
            stage_tile16(gwarp + (tl + 2) * 256, xs_base + (tl & 1) * 4096, l);
    }

    // ---- Sg/Sb warp reduce (x0.5: every row counted by both lane halves) ----
#pragma unroll
    for (int s = 0; s < 8; ++s) {
        float gv = gacc[s], bv = bacc[s];
#pragma unroll
        for (int off = 16; off; off >>= 1) {
            gv += __shfl_xor_sync(0xffffffffu, gv, off);
            bv += __shfl_xor_sync(0xffffffffu, bv, off);
        }
        if (l == 0) { tail[16 + w * 8 + s] = gv * 0.5f; tail[48 + w * 8 + s] = bv * 0.5f; }
    }
    __syncthreads();   // all warps done; xs reusable as reduction scratch

    // ---- cross-warp Pacc reduce (fixed order) ----
    float4* red4 = xs;   // [w][128] float4 = [w][s*16+e4]
#pragma unroll
    for (int ss = 0; ss < 4; ++ss) {
        float x0, x1, x2, x3;
        F2UNPK(x0, x1, p2[2 * ss]);
        F2UNPK(x2, x3, p2[2 * ss + 1]);
        red4[w * 128 + (4 * g2 + ss) * 16 + e4] = make_float4(x0, x1, x2, x3);
    }
    __syncthreads();

    float4* gp4 = g_part4 + ((size_t)(b * NBLKX + blockIdx.x)) * 132;
    {
        float4 a = red4[t], bb2 = red4[128 + t], c = red4[256 + t], d = red4[384 + t];
        float4 o;
        o.x = ((a.x + bb2.x) + c.x) + d.x;
        o.y = ((a.y + bb2.y) + c.y) + d.y;
        o.z = ((a.z + bb2.z) + c.z) + d.z;
        o.w = ((a.w + bb2.w) + c.w) + d.w;
        gp4[t] = o;
    }
    if (t < 16) {
        const float* src = tail + 16 + (t >= 8 ? 32 : 0) + (t & 7);
        float v = ((src[0] + src[8]) + src[16]) + src[24];
        reinterpret_cast<float*>(gp4)[512 + (t >= 8 ? 8 : 0) + (t & 7)] = v;
    }
}

// ---------------------------------------------------------------------------
// slot update: one block per (b,s)
// ---------------------------------------------------------------------------
__global__ void __launch_bounds__(128) k_update(
    const float* __restrict__ lng,  const float* __restrict__ lnb,
    const float* __restrict__ lnsg, const float* __restrict__ lnsb,
    const float* __restrict__ lnmg, const float* __restrict__ lnmb,
    const float* __restrict__ Wq,   const float* __restrict__ Wk,
    const float* __restrict__ Wv,
    const float* __restrict__ W_ih, const float* __restrict__ W_hh,
    const float* __restrict__ b_ih, const float* __restrict__ b_hh,
    const float* __restrict__ W1,   const float* __restrict__ b1,
    const float* __restrict__ W2,   const float* __restrict__ b2,
    float* __restrict__ out, int last)
{
    __shared__ __align__(16) float P[64], Uv[64], upds[64], slp[64];
    __shared__ __align__(16) float gi[192], gh[192], updh[64], mln[64];
    __shared__ __align__(16) float hhs[128], snew[64];
    __shared__ __align__(16) float lns[64], qv[64], qtv[64], hpart[128];
    __shared__ float sred[4];
    __shared__ float sSg, sSb;

    int bs = blockIdx.x, b = bs >> 3, s = bs & 7, t = threadIdx.x;

    const float* pb = reinterpret_cast<const float*>(g_part4) + (size_t)b * NBLKX * PREC;
    {
        int e = t & 63, h = t >> 6;
        const float* src = pb + (size_t)h * 16 * PREC + s * 64 + e;
        float acc = 0.f;
#pragma unroll 8
        for (int blk = 0; blk < 16; ++blk) acc += src[(size_t)blk * PREC];
        hpart[t] = acc;
    }
    if (t < 4) {
        int which = t & 1, h = t >> 1;
        const float* src = pb + (size_t)h * 16 * PREC + 512 + which * 8 + s;
        float acc = 0.f;
#pragma unroll 8
        for (int blk = 0; blk < 16; ++blk) acc += src[(size_t)blk * PREC];
        sred[t] = acc;
    }
    if (t < 64) slp[t] = g_slots[b * 512 + s * 64 + t];
    __syncthreads();
    if (t < 64) P[t] = hpart[t] + hpart[t + 64];
    if (t == 0) { sSg = sred[0] + sred[2]; sSb = sred[1] + sred[3]; }
    __syncthreads();

    if (t < 64) Uv[t] = fmaf(lng[t], P[t] - sSb, lnb[t] * sSg) / sSg;
    __syncthreads();

    {
        int dd = t & 63, h = t >> 6;
        const float4* wr = (const float4*)(Wv + dd * 64) + h * 8;
        const float4* uv = (const float4*)Uv + h * 8;
        float r = dot8x4(uv, wr);
        __syncthreads();
        hpart[t] = r;
    }
    __syncthreads();
    if (t < 64) upds[t] = hpart[t] + hpart[t + 64];
    __syncthreads();

#pragma unroll
    for (int k = 0; k < 3; ++k) {
        int id = t + 128 * k;
        if (id < 192) {
            int j = id;
            gi[j] = dot16x4((const float4*)upds, (const float4*)(W_ih + j * 64), b_ih[j]);
        } else {
            int j = id - 192;
            gh[j] = dot16x4((const float4*)slp, (const float4*)(W_hh + j * 64), b_hh[j]);
        }
    }
    __syncthreads();

    if (t < 64) {
        float r = sigm(gi[t]      + gh[t]);
        float z = sigm(gi[64 + t] + gh[64 + t]);
        float n = tanhf(fmaf(r, gh[128 + t], gi[128 + t]));
        updh[t] = fmaf(z, slp[t] - n, n);
    }
    __syncthreads();

    ln64_warp(updh, mln, lnmg, lnmb, t);
    __syncthreads();

    hhs[t] = fmaxf(dot16x4((const float4*)mln, (const float4*)(W1 + t * 64), b1[t]), 0.f);
    __syncthreads();

    {
        int dd = t & 63, h = t >> 6;
        const float4* wr = (const float4*)(W2 + dd * 128) + h * 16;
        const float4* hv = (const float4*)hhs + h * 16;
        hpart[t] = dot16x4(hv, wr, 0.f);
    }
    __syncthreads();
    if (t < 64) {
        float v = updh[t] + b2[t] + (hpart[t] + hpart[t + 64]);
        snew[t] = v;
        g_slots[b * 512 + s * 64 + t] = v;
        if (last) out[b * 512 + s * 64 + t] = v;
    }
    __syncthreads();

    if (!last)
        prep_slot(b, s, t, snew, lns, qv, qtv, hpart, lnsg, lnsb, Wq, Wk, lng, lnb);
}

// ---------------------------------------------------------------------------
extern "C" void kernel_launch(void* const* d_in, const int* in_sizes, int n_in,
                              void* d_out, int out_size)
{
    const float* x     = (const float*)d_in[0];
    const float* noise = (const float*)d_in[1];
    const float* mu    = (const float*)d_in[2];
    const float* lsig  = (const float*)d_in[3];
    const float* lng   = (const float*)d_in[4];
    const float* lnb   = (const float*)d_in[5];
    const float* lnsg  = (const float*)d_in[6];
    const float* lnsb  = (const float*)d_in[7];
    const float* lnmg  = (const float*)d_in[8];
    const float* lnmb  = (const float*)d_in[9];
    const float* Wq    = (const float*)d_in[10];
    const float* Wk    = (const float*)d_in[11];
    const float* Wv    = (const float*)d_in[12];
    const float* W_ih  = (const float*)d_in[13];
    const float* W_hh  = (const float*)d_in[14];
    const float* b_ih  = (const float*)d_in[15];
    const float* b_hh  = (const float*)d_in[16];
    const float* W1    = (const float*)d_in[17];
    const float* b1    = (const float*)d_in[18];
    const float* W2    = (const float*)d_in[19];
    const float* b2    = (const float*)d_in[20];
    float* out = (float*)d_out;

    cudaFuncSetAttribute(k_pass, cudaFuncAttributeMaxDynamicSharedMemorySize, SMEM_BYTES);

    k_init<<<BB * SS, 128>>>(noise, mu, lsig, lnsg, lnsb, Wq, Wk, lng, lnb);

    for (int it = 0; it < 3; ++it) {
        k_pass<<<dim3(NBLKX, BB), PASS_THREADS, SMEM_BYTES>>>((const float4*)x);
        k_update<<<BB * SS, 128>>>(lng, lnb, lnsg, lnsb, lnmg, lnmb,
                                   Wq, Wk, Wv, W_ih, W_hh, b_ih, b_hh,
                                   W1, b1, W2, b2, out, it == 2);
    }
}

// round 10
// speedup vs baseline: 1.0212x; 1.0120x over previous
#include <cuda_runtime.h>

// ---------------------------------------------------------------------------
// SlotAttention fused. B=32, N=16384, S=8, D=64, H=128, ITERS=3.
// k_pass: per-warp cp.async pipelined 32-row tiles (ring-2), folded-LN logits
//         + softmax + rank-1 accum, f32x2 FMAs, no block syncs in mainloop.
//         (round-6 architecture: best measured at 44.8us)
// k_update/k_init: one block per (batch, slot). Fixed-order reductions,
//         coalesced partial reduce, ILP-4 weight dots.
// ---------------------------------------------------------------------------

#define BB 32
#define NN 16384
#define SS 8
#define DD 64
#define HH 128
#define NBLKX 32                 // pass blocks per batch (512 rows each)
#define WTILES 4                 // warp-tiles per warp (32 rows each)
#define PREC 528                 // floats per record: 512 Pacc + 8 Sg + 8 Sb
#define PASS_THREADS 128
// smem: xs 4096*16 + as4 256*16 + wts 128*16 + tail 80*4 = 72000 -> pad 72064
#define SMEM_BYTES 72064

typedef unsigned long long ull;

__device__ float  g_slots[BB * SS * DD];
__device__ float4 g_wts4[BB * 128];          // [b][k=0..15][s=0..7]
__device__ float  g_c0[BB][SS];
__device__ float  g_c1[BB][SS];
__device__ float4 g_part4[(size_t)BB * NBLKX * 132];

#define F2FMA(d, a, b) asm("fma.rn.f32x2 %0, %1, %2, %0;" : "+l"(d) : "l"(a), "l"(b))
#define F2ADD(d, a, b) asm("add.rn.f32x2 %0, %1, %2;" : "=l"(d) : "l"(a), "l"(b))
#define F2PACK(v, lo, hi) asm("mov.b64 %0, {%1, %2};" : "=l"(v) : "f"(lo), "f"(hi))
#define F2UNPK(lo, hi, v) asm("mov.b64 {%0, %1}, %2;" : "=f"(lo), "=f"(hi) : "l"(v))

__device__ __forceinline__ float sigm(float x) { return 1.f / (1.f + __expf(-x)); }

__global__ void k_nop() {}   // shifts ncu -s 5 onto k_update#2

// dot of 16 float4 vs 16 float4, ILP-4 accumulators, fixed combine order
__device__ __forceinline__ float dot16x4(const float4* a, const float4* w, float bias) {
    float a0 = 0.f, a1 = 0.f, a2 = 0.f, a3 = 0.f;
#pragma unroll
    for (int e = 0; e < 4; ++e) {
        float4 x0 = a[e],      w0 = w[e];
        float4 x1 = a[e + 4],  w1 = w[e + 4];
        float4 x2 = a[e + 8],  w2 = w[e + 8];
        float4 x3 = a[e + 12], w3 = w[e + 12];
        a0 = fmaf(x0.x, w0.x, fmaf(x0.y, w0.y, fmaf(x0.z, w0.z, fmaf(x0.w, w0.w, a0))));
        a1 = fmaf(x1.x, w1.x, fmaf(x1.y, w1.y, fmaf(x1.z, w1.z, fmaf(x1.w, w1.w, a1))));
        a2 = fmaf(x2.x, w2.x, fmaf(x2.y, w2.y, fmaf(x2.z, w2.z, fmaf(x2.w, w2.w, a2))));
        a3 = fmaf(x3.x, w3.x, fmaf(x3.y, w3.y, fmaf(x3.z, w3.z, fmaf(x3.w, w3.w, a3))));
    }
    return bias + ((a0 + a1) + (a2 + a3));
}
__device__ __forceinline__ float dot8x4(const float4* a, const float4* w) {
    float a0 = 0.f, a1 = 0.f;
#pragma unroll
    for (int e = 0; e < 4; ++e) {
        float4 x0 = a[e],     w0 = w[e];
        float4 x1 = a[e + 4], w1 = w[e + 4];
        a0 = fmaf(x0.x, w0.x, fmaf(x0.y, w0.y, fmaf(x0.z, w0.z, fmaf(x0.w, w0.w, a0))));
        a1 = fmaf(x1.x, w1.x, fmaf(x1.y, w1.y, fmaf(x1.z, w1.z, fmaf(x1.w, w1.w, a1))));
    }
    return a0 + a1;
}

__device__ __forceinline__ void ln64_warp(const float* in, float* out,
                                          const float* __restrict__ g,
                                          const float* __restrict__ bt, int t) {
    if (t < 32) {
        float v0 = in[t], v1 = in[t + 32];
        float sum = v0 + v1;
        float sq  = fmaf(v0, v0, v1 * v1);
#pragma unroll
        for (int off = 16; off; off >>= 1) {
            sum += __shfl_xor_sync(0xffffffffu, sum, off);
            sq  += __shfl_xor_sync(0xffffffffu, sq,  off);
        }
        float m    = sum * (1.f / 64.f);
        float istd = rsqrtf(fmaf(sq, 1.f / 64.f, -m * m) + 1e-5f);
        out[t]      = fmaf((v0 - m) * istd, g[t],      bt[t]);
        out[t + 32] = fmaf((v1 - m) * istd, g[t + 32], bt[t + 32]);
    }
}

// ---------------------------------------------------------------------------
__device__ __forceinline__ void prep_slot(
    int b, int s, int t,
    const float* snew, float* lns, float* qv, float* qtv, float* hpart,
    const float* __restrict__ lnsg, const float* __restrict__ lnsb,
    const float* __restrict__ Wq,   const float* __restrict__ Wk,
    const float* __restrict__ lng,  const float* __restrict__ lnb)
{
    ln64_warp(snew, lns, lnsg, lnsb, t);
    __syncthreads();
    {
        int dd = t & 63, h = t >> 6;
        const float4* wr = (const float4*)(Wq + dd * 64) + h * 8;
        const float4* lv = (const float4*)lns + h * 8;
        hpart[t] = dot8x4(lv, wr);
    }
    __syncthreads();
    if (t < 64) qv[t] = (hpart[t] + hpart[t + 64]) * 0.125f;
    __syncthreads();
    {
        int e = t & 63, h = t >> 6;
        float acc = 0.f;
        const float* wk = Wk + (h * 32) * 64 + e;
#pragma unroll 8
        for (int dd = 0; dd < 32; ++dd) acc = fmaf(qv[h * 32 + dd], wk[dd * 64], acc);
        hpart[t] = acc;
    }
    __syncthreads();
    if (t < 64) qtv[t] = hpart[t] + hpart[t + 64];
    __syncthreads();
    if (t < 64) {
        int k = t >> 2, j = t & 3;
        reinterpret_cast<float*>(g_wts4 + b * 128)[(k * 8 + s) * 4 + j] = lng[t] * qtv[t];
    }
    if (t < 32) {
        float p1 = fmaf(lng[t + 32], qtv[t + 32], lng[t] * qtv[t]);
        float p0 = fmaf(lnb[t + 32], qtv[t + 32], lnb[t] * qtv[t]);
#pragma unroll
        for (int off = 16; off; off >>= 1) {
            p1 += __shfl_xor_sync(0xffffffffu, p1, off);
            p0 += __shfl_xor_sync(0xffffffffu, p0, off);
        }
        if (t == 0) { g_c1[b][s] = p1; g_c0[b][s] = p0; }
    }
}

// ---------------------------------------------------------------------------
__global__ void __launch_bounds__(128) k_init(
    const float* __restrict__ noise, const float* __restrict__ mu,
    const float* __restrict__ lsig,
    const float* __restrict__ lnsg, const float* __restrict__ lnsb,
    const float* __restrict__ Wq,   const float* __restrict__ Wk,
    const float* __restrict__ lng,  const float* __restrict__ lnb)
{
    __shared__ __align__(16) float snew[64], lns[64], qv[64], qtv[64], hpart[128];
    int bs = blockIdx.x, b = bs >> 3, s = bs & 7, t = threadIdx.x;
    if (t < 64) {
        int idx = s * 64 + t;
        float v = fmaf(__expf(lsig[idx]), noise[b * 512 + idx], mu[idx]);
        snew[t] = v;
        g_slots[b * 512 + idx] = v;
    }
    __syncthreads();
    prep_slot(b, s, t, snew, lns, qv, qtv, hpart, lnsg, lnsb, Wq, Wk, lng, lnb);
}

// ---------------------------------------------------------------------------
// stage one 32-row warp-tile (8KB) via cp.async (lane l issues 16 x 16B)
// ---------------------------------------------------------------------------
__device__ __forceinline__ void stage_tile(const float4* __restrict__ gsrc,
                                           unsigned sdst, int l)
{
#pragma unroll
    for (int j = 0; j < 16; ++j) {
        int flat = j * 32 + l;
        int row = flat >> 4, k = flat & 15;
        unsigned dst = sdst + (unsigned)((row * 16 + (k ^ (row & 15))) * 16);
        asm volatile("cp.async.cg.shared.global [%0], [%1], 16;"
                     :: "r"(dst), "l"(gsrc + flat));
    }
    asm volatile("cp.async.commit_group;");
}

// ---------------------------------------------------------------------------
// the big fused pass (round-6 architecture). dynamic smem (float4 units):
//   [0,4096)    xs   : 4 warps x 2 ring x 512 (64KB)
//   [4096,4352) as4  : 4 warps x 64 (4KB)
//   [4352,4480) wts  : 128 (2KB)
//   tail floats: c0s[8], c1s[8], redSg[4][8], redSb[4][8]
// ---------------------------------------------------------------------------
__global__ void __launch_bounds__(PASS_THREADS) k_pass(const float4* __restrict__ x4)
{
    extern __shared__ __align__(16) float4 smem[];
    float4* xs   = smem;
    float4* as4  = smem + 4096;
    float4* wts  = smem + 4352;
    float*  tail = (float*)(smem + 4480);   // 80 floats

    const int b = blockIdx.y;
    const int t = threadIdx.x;
    const int w = t >> 5, l = t & 31;

    unsigned smem_u32;
    { size_t a = __cvta_generic_to_shared(xs); smem_u32 = (unsigned)a; }
    const unsigned xs_base = smem_u32 + (unsigned)(w * 1024 * 16);

    // prologue: prefetch warp-tiles 0 and 1
    const float4* gwarp = x4 + ((size_t)b * NN + (size_t)blockIdx.x * 512 + w * 128) * 16;
    stage_tile(gwarp,       xs_base,        l);
    stage_tile(gwarp + 512, xs_base + 8192, l);

    wts[t] = g_wts4[b * 128 + t];
    if (t < 8)  tail[t]     = g_c0[b][t];
    if (t >= 8 && t < 16) tail[t] = g_c1[b][t - 8];
    __syncthreads();

    float c0r[8], c1r[8], gacc[8], bacc[8];
    ull p2[8];
#pragma unroll
    for (int s = 0; s < 8; ++s) {
        c0r[s] = tail[s]; c1r[s] = tail[8 + s];
        gacc[s] = 0.f; bacc[s] = 0.f; p2[s] = 0ULL;
    }

    const ulonglong2* wt2 = reinterpret_cast<const ulonglong2*>(wts);
    float4* as4w = as4 + w * 64;
    const int g2 = l >> 4, e4 = l & 15;

#pragma unroll
    for (int tl = 0; tl < WTILES; ++tl) {
        if (tl == WTILES - 1) asm volatile("cp.async.wait_group 0;" ::: "memory");
        else                  asm volatile("cp.async.wait_group 1;" ::: "memory");
        __syncwarp();

        const ulonglong2* xs2w = reinterpret_cast<const ulonglong2*>(
            xs + w * 1024 + (tl & 1) * 512);

        // ---- phase 1: lane l owns row l of this 32-row tile ----
        {
            ull d2[8];
#pragma unroll
            for (int s = 0; s < 8; ++s) d2[s] = 0ULL;
            ull sum2 = 0ULL, sqa = 0ULL, sqb = 0ULL;
            const int rb = l * 16, ro = l & 15;
#pragma unroll
            for (int k = 0; k < 16; ++k) {
                ulonglong2 v = xs2w[rb + (k ^ ro)];
                ull tv; F2ADD(tv, v.x, v.y); F2ADD(sum2, sum2, tv);
                F2FMA(sqa, v.x, v.x);
                F2FMA(sqb, v.y, v.y);
#pragma unroll
                for (int s = 0; s < 8; ++s) {
                    ulonglong2 wv = wt2[k * 8 + s];
                    F2FMA(d2[s], v.x, wv.x);
                    F2FMA(d2[s], v.y, wv.y);
                }
            }
            float slo, shi; F2UNPK(slo, shi, sum2);
            float sum = slo + shi;
            float qa0, qa1, qb0, qb1;
            F2UNPK(qa0, qa1, sqa); F2UNPK(qb0, qb1, sqb);
            float sq = (qa0 + qa1) + (qb0 + qb1);
            float m    = sum * (1.f / 64.f);
            float istd = rsqrtf(fmaf(sq, 1.f / 64.f, -m * m) + 1e-5f);
            float lo[8], mx = -3.4e38f;
#pragma unroll
            for (int s = 0; s < 8; ++s) {
                float dlo, dhi; F2UNPK(dlo, dhi, d2[s]);
                float d = dlo + dhi;
                lo[s] = fmaf(istd, fmaf(-m, c1r[s], d), c0r[s]);
                mx = fmaxf(mx, lo[s]);
            }
            float pr[8], ps = 0.f;
#pragma unroll
            for (int s = 0; s < 8; ++s) { pr[s] = __expf(lo[s] - mx); ps += pr[s]; }
            float rc  = 1.f / ps;
            float tmi = m * istd;
            float al[8];
#pragma unroll
            for (int s = 0; s < 8; ++s) {
                float a = fmaf(pr[s], rc, 1e-8f);   // softmax + EPS
                gacc[s] += a;
                bacc[s] = fmaf(a, tmi, bacc[s]);
                al[s]   = a * istd;
            }
            as4w[l * 2 + 0] = make_float4(al[0], al[1], al[2], al[3]);
            as4w[l * 2 + 1] = make_float4(al[4], al[5], al[6], al[7]);
        }
        __syncwarp();

        // ---- phase 2: lane (g2, e4) owns slots 4g2..4g2+3 x elems 4e4..4e4+3 ----
#pragma unroll 4
        for (int r = 0; r < 32; ++r) {
            float4 av = as4w[r * 2 + g2];
            ulonglong2 xq = xs2w[r * 16 + (e4 ^ (r & 15))];
            ull a0, a1, a2, a3;
            F2PACK(a0, av.x, av.x); F2PACK(a1, av.y, av.y);
            F2PACK(a2, av.z, av.z); F2PACK(a3, av.w, av.w);
            F2FMA(p2[0], xq.x, a0); F2FMA(p2[1], xq.y, a0);
            F2FMA(p2[2], xq.x, a1); F2FMA(p2[3], xq.y, a1);
            F2FMA(p2[4], xq.x, a2); F2FMA(p2[5], xq.y, a2);
            F2FMA(p2[6], xq.x, a3); F2FMA(p2[7], xq.y, a3);
        }
        __syncwarp();

        if (tl < WTILES - 2)
            stage_tile(gwarp + (tl + 2) * 512, xs_base + (tl & 1) * 8192, l);
    }

    // ---- Sg/Sb warp reduce ----
#pragma unroll
    for (int s = 0; s < 8; ++s) {
        float gv = gacc[s], bv = bacc[s];
#pragma unroll
        for (int off = 16; off; off >>= 1) {
            gv += __shfl_xor_sync(0xffffffffu, gv, off);
            bv += __shfl_xor_sync(0xffffffffu, bv, off);
        }
        if (l == 0) { tail[16 + w * 8 + s] = gv; tail[48 + w * 8 + s] = bv; }
    }
    __syncthreads();   // all warps done; xs reusable as reduction scratch

    // ---- cross-warp Pacc reduce (fixed order) ----
    float4* red4 = xs;   // [w][128] float4 = [w][s*16+e4]
#pragma unroll
    for (int ss = 0; ss < 4; ++ss) {
        float x0, x1, x2, x3;
        F2UNPK(x0, x1, p2[2 * ss]);
        F2UNPK(x2, x3, p2[2 * ss + 1]);
        red4[w * 128 + (4 * g2 + ss) * 16 + e4] = make_float4(x0, x1, x2, x3);
    }
    __syncthreads();

    float4* gp4 = g_part4 + ((size_t)(b * NBLKX + blockIdx.x)) * 132;
    {
        float4 a = red4[t], bb2 = red4[128 + t], c = red4[256 + t], d = red4[384 + t];
        float4 o;
        o.x = ((a.x + bb2.x) + c.x) + d.x;
        o.y = ((a.y + bb2.y) + c.y) + d.y;
        o.z = ((a.z + bb2.z) + c.z) + d.z;
        o.w = ((a.w + bb2.w) + c.w) + d.w;
        gp4[t] = o;
    }
    if (t < 16) {
        const float* src = tail + 16 + (t >= 8 ? 32 : 0) + (t & 7);
        float v = ((src[0] + src[8]) + src[16]) + src[24];
        reinterpret_cast<float*>(gp4)[512 + (t >= 8 ? 8 : 0) + (t & 7)] = v;
    }
}

// ---------------------------------------------------------------------------
// slot update: one block per (b,s). Coalesced partial reduce, ILP dots.
// ---------------------------------------------------------------------------
__global__ void __launch_bounds__(128) k_update(
    const float* __restrict__ lng,  const float* __restrict__ lnb,
    const float* __restrict__ lnsg, const float* __restrict__ lnsb,
    const float* __restrict__ lnmg, const float* __restrict__ lnmb,
    const float* __restrict__ Wq,   const float* __restrict__ Wk,
    const float* __restrict__ Wv,
    const float* __restrict__ W_ih, const float* __restrict__ W_hh,
    const float* __restrict__ b_ih, const float* __restrict__ b_hh,
    const float* __restrict__ W1,   const float* __restrict__ b1,
    const float* __restrict__ W2,   const float* __restrict__ b2,
    float* __restrict__ out, int last)
{
    __shared__ __align__(16) float P[64], Uv[64], upds[64], slp[64];
    __shared__ __align__(16) float gi[192], gh[192], updh[64], mln[64];
    __shared__ __align__(16) float hhs[128], snew[64];
    __shared__ __align__(16) float lns[64], qv[64], qtv[64], hpart[128];
    __shared__ __align__(16) float4 pg4[4][16];    // phase-A group partials
    __shared__ float sred[8];
    __shared__ float sSg, sSb;

    int bs = blockIdx.x, b = bs >> 3, s = bs & 7, t = threadIdx.x;

    // ---- A: coalesced fixed-order reduce of 32 records for this slot ----
    const float4* pb4 = g_part4 + (size_t)b * NBLKX * 132;
    if (t < 64) {
        int e4 = t & 15, grp = t >> 4;               // 4 groups x 8 records
        const float4* src = pb4 + (size_t)grp * 8 * 132 + s * 16 + e4;
        float4 acc = make_float4(0.f, 0.f, 0.f, 0.f);
#pragma unroll
        for (int j = 0; j < 8; ++j) {
            float4 v = src[(size_t)j * 132];
            acc.x += v.x; acc.y += v.y; acc.z += v.z; acc.w += v.w;
        }
        pg4[grp][e4] = acc;
    } else if (t < 72) {
        // Sg/Sb: 8 threads, each reduces 8 records (scalar), fixed order
        int which = (t - 64) >> 2;                   // 0 = Sg, 1 = Sb
        int grp = (t - 64) & 3;                      // 4 groups x 8 records
        const float* src = reinterpret_cast<const float*>(pb4)
                         + (size_t)grp * 8 * PREC + 512 + which * 8 + s;
        float acc = 0.f;
#pragma unroll
        for (int j = 0; j < 8; ++j) acc += src[(size_t)j * PREC];
        sred[t - 64] = acc;
    }
    // slp load: threads 64..127 cover all 64 elements (fixes round-9 gap)
    if (t >= 64) slp[t - 64] = g_slots[b * 512 + s * 64 + (t - 64)];
    __syncthreads();
    if (t < 16) {
        float4 a = pg4[0][t], bg = pg4[1][t], c = pg4[2][t], d = pg4[3][t];
        float4 o;
        o.x = ((a.x + bg.x) + c.x) + d.x;
        o.y = ((a.y + bg.y) + c.y) + d.y;
        o.z = ((a.z + bg.z) + c.z) + d.z;
        o.w = ((a.w + bg.w) + c.w) + d.w;
        reinterpret_cast<float4*>(P)[t] = o;
    }
    if (t == 0) sSg = ((sred[0] + sred[1]) + sred[2]) + sred[3];
    if (t == 1) sSb = ((sred[4] + sred[5]) + sred[6]) + sred[7];
    __syncthreads();

    // ---- B: U[e] = (g*(P - Sb) + b*Sg)/Sg ----
    if (t < 64) Uv[t] = fmaf(lng[t], P[t] - sSb, lnb[t] * sSg) / sSg;
    __syncthreads();

    // ---- C: upds = U @ Wv^T (half-split) ----
    {
        int dd = t & 63, h = t >> 6;
        const float4* wr = (const float4*)(Wv + dd * 64) + h * 8;
        const float4* uv = (const float4*)Uv + h * 8;
        float r = dot8x4(uv, wr);
        __syncthreads();
        hpart[t] = r;
    }
    __syncthreads();
    if (t < 64) upds[t] = hpart[t] + hpart[t + 64];
    __syncthreads();

    // ---- D: GRU pre-activations (384 dots / 128 threads = 3 each) ----
#pragma unroll
    for (int k = 0; k < 3; ++k) {
        int id = t + 128 * k;
        if (id < 192) {
            int j = id;
            gi[j] = dot16x4((const float4*)upds, (const float4*)(W_ih + j * 64), b_ih[j]);
        } else {
            int j = id - 192;
            gh[j] = dot16x4((const float4*)slp, (const float4*)(W_hh + j * 64), b_hh[j]);
        }
    }
    __syncthreads();

    // ---- E: gates ----
    if (t < 64) {
        float r = sigm(gi[t]      + gh[t]);
        float z = sigm(gi[64 + t] + gh[64 + t]);
        float n = tanhf(fmaf(r, gh[128 + t], gi[128 + t]));
        updh[t] = fmaf(z, slp[t] - n, n);
    }
    __syncthreads();

    // ---- F: LN(updh) ----
    ln64_warp(updh, mln, lnmg, lnmb, t);
    __syncthreads();

    // ---- G: hidden = relu(mln @ W1^T + b1) ----
    hhs[t] = fmaxf(dot16x4((const float4*)mln, (const float4*)(W1 + t * 64), b1[t]), 0.f);
    __syncthreads();

    // ---- H: snew = updh + hh @ W2^T + b2 (half-split over 128) ----
    {
        int dd = t & 63, h = t >> 6;
        const float4* wr = (const float4*)(W2 + dd * 128) + h * 16;
        const float4* hv = (const float4*)hhs + h * 16;
        hpart[t] = dot16x4(hv, wr, 0.f);
    }
    __syncthreads();
    if (t < 64) {
        float v = updh[t] + b2[t] + (hpart[t] + hpart[t + 64]);
        snew[t] = v;
        g_slots[b * 512 + s * 64 + t] = v;
        if (last) out[b * 512 + s * 64 + t] = v;
    }
    __syncthreads();

    if (!last)
        prep_slot(b, s, t, snew, lns, qv, qtv, hpart, lnsg, lnsb, Wq, Wk, lng, lnb);
}

// ---------------------------------------------------------------------------
extern "C" void kernel_launch(void* const* d_in, const int* in_sizes, int n_in,
                              void* d_out, int out_size)
{
    const float* x     = (const float*)d_in[0];
    const float* noise = (const float*)d_in[1];
    const float* mu    = (const float*)d_in[2];
    const float* lsig  = (const float*)d_in[3];
    const float* lng   = (const float*)d_in[4];
    const float* lnb   = (const float*)d_in[5];
    const float* lnsg  = (const float*)d_in[6];
    const float* lnsb  = (const float*)d_in[7];
    const float* lnmg  = (const float*)d_in[8];
    const float* lnmb  = (const float*)d_in[9];
    const float* Wq    = (const float*)d_in[10];
    const float* Wk    = (const float*)d_in[11];
    const float* Wv    = (const float*)d_in[12];
    const float* W_ih  = (const float*)d_in[13];
    const float* W_hh  = (const float*)d_in[14];
    const float* b_ih  = (const float*)d_in[15];
    const float* b_hh  = (const float*)d_in[16];
    const float* W1    = (const float*)d_in[17];
    const float* b1    = (const float*)d_in[18];
    const float* W2    = (const float*)d_in[19];
    const float* b2    = (const float*)d_in[20];
    float* out = (float*)d_out;

    cudaFuncSetAttribute(k_pass, cudaFuncAttributeMaxDynamicSharedMemorySize, SMEM_BYTES);

    k_nop<<<1, 32>>>();   // aligns ncu -s 5 onto k_update#2
    k_init<<<BB * SS, 128>>>(noise, mu, lsig, lnsg, lnsb, Wq, Wk, lng, lnb);

    for (int it = 0; it < 3; ++it) {
        k_pass<<<dim3(NBLKX, BB), PASS_THREADS, SMEM_BYTES>>>((const float4*)x);
        k_update<<<BB * SS, 128>>>(lng, lnb, lnsg, lnsb, lnmg, lnmb,
                                   Wq, Wk, Wv, W_ih, W_hh, b_ih, b_hh,
                                   W1, b1, W2, b2, out, it == 2);
    }
}

// round 11
// speedup vs baseline: 1.0429x; 1.0213x over previous
#include <cuda_runtime.h>

// ---------------------------------------------------------------------------
// SlotAttention fused. B=32, N=16384, S=8, D=64, H=128, ITERS=3.
// k_pass: per-warp cp.async pipelined 32-row tiles (ring-2), folded-LN logits
//         + softmax + rank-1 accum, f32x2 FMAs (round-6 architecture, 44.8us).
// k_update: 128 blocks; each stages ALL weights into 223KB smem via cp.async
//         (7 groups, just-in-time waits) and runs the slot-update chain for
//         TWO (b,s) pairs, eliminating the DRAM-cold-weight latency chain.
// ---------------------------------------------------------------------------

#define BB 32
#define NN 16384
#define SS 8
#define DD 64
#define HH 128
#define NBLKX 32                 // pass blocks per batch (512 rows each)
#define WTILES 4                 // warp-tiles per warp (32 rows each)
#define PREC 528                 // floats per record: 512 Pacc + 8 Sg + 8 Sb
#define PASS_THREADS 128
#define SMEM_BYTES 72064         // k_pass smem
#define UPD_SMEM (13952 * 16)    // k_update smem: 223232 bytes

typedef unsigned long long ull;

__device__ float  g_slots[BB * SS * DD];
__device__ float4 g_wts4[BB * 128];          // [b][k=0..15][s=0..7]
__device__ float  g_c0[BB][SS];
__device__ float  g_c1[BB][SS];
__device__ float4 g_part4[(size_t)BB * NBLKX * 132];

#define F2FMA(d, a, b) asm("fma.rn.f32x2 %0, %1, %2, %0;" : "+l"(d) : "l"(a), "l"(b))
#define F2ADD(d, a, b) asm("add.rn.f32x2 %0, %1, %2;" : "=l"(d) : "l"(a), "l"(b))
#define F2PACK(v, lo, hi) asm("mov.b64 %0, {%1, %2};" : "=l"(v) : "f"(lo), "f"(hi))
#define F2UNPK(lo, hi, v) asm("mov.b64 {%0, %1}, %2;" : "=f"(lo), "=f"(hi) : "l"(v))

#define CPA(dst, src) asm volatile("cp.async.cg.shared.global [%0], [%1], 16;" \
                                   :: "r"(dst), "l"(src))
#define CPCOMMIT() asm volatile("cp.async.commit_group;")
#define WAITG(n) asm volatile("cp.async.wait_group " #n ";" ::: "memory")

__device__ __forceinline__ float sigm(float x) { return 1.f / (1.f + __expf(-x)); }

// dot of 16 float4 vs 16 float4, ILP-4 accumulators, fixed combine order
__device__ __forceinline__ float dot16x4(const float4* a, const float4* w, float bias) {
    float a0 = 0.f, a1 = 0.f, a2 = 0.f, a3 = 0.f;
#pragma unroll
    for (int e = 0; e < 4; ++e) {
        float4 x0 = a[e],      w0 = w[e];
        float4 x1 = a[e + 4],  w1 = w[e + 4];
        float4 x2 = a[e + 8],  w2 = w[e + 8];
        float4 x3 = a[e + 12], w3 = w[e + 12];
        a0 = fmaf(x0.x, w0.x, fmaf(x0.y, w0.y, fmaf(x0.z, w0.z, fmaf(x0.w, w0.w, a0))));
        a1 = fmaf(x1.x, w1.x, fmaf(x1.y, w1.y, fmaf(x1.z, w1.z, fmaf(x1.w, w1.w, a1))));
        a2 = fmaf(x2.x, w2.x, fmaf(x2.y, w2.y, fmaf(x2.z, w2.z, fmaf(x2.w, w2.w, a2))));
        a3 = fmaf(x3.x, w3.x, fmaf(x3.y, w3.y, fmaf(x3.z, w3.z, fmaf(x3.w, w3.w, a3))));
    }
    return bias + ((a0 + a1) + (a2 + a3));
}
__device__ __forceinline__ float dot8x4(const float4* a, const float4* w) {
    float a0 = 0.f, a1 = 0.f;
#pragma unroll
    for (int e = 0; e < 4; ++e) {
        float4 x0 = a[e],     w0 = w[e];
        float4 x1 = a[e + 4], w1 = w[e + 4];
        a0 = fmaf(x0.x, w0.x, fmaf(x0.y, w0.y, fmaf(x0.z, w0.z, fmaf(x0.w, w0.w, a0))));
        a1 = fmaf(x1.x, w1.x, fmaf(x1.y, w1.y, fmaf(x1.z, w1.z, fmaf(x1.w, w1.w, a1))));
    }
    return a0 + a1;
}

__device__ __forceinline__ void ln64_warp(const float* in, float* out,
                                          const float* g,
                                          const float* bt, int t) {
    if (t < 32) {
        float v0 = in[t], v1 = in[t + 32];
        float sum = v0 + v1;
        float sq  = fmaf(v0, v0, v1 * v1);
#pragma unroll
        for (int off = 16; off; off >>= 1) {
            sum += __shfl_xor_sync(0xffffffffu, sum, off);
            sq  += __shfl_xor_sync(0xffffffffu, sq,  off);
        }
        float m    = sum * (1.f / 64.f);
        float istd = rsqrtf(fmaf(sq, 1.f / 64.f, -m * m) + 1e-5f);
        out[t]      = fmaf((v0 - m) * istd, g[t],      bt[t]);
        out[t + 32] = fmaf((v1 - m) * istd, g[t + 32], bt[t + 32]);
    }
}

// ---------------------------------------------------------------------------
// per-(b,s) prep: folded pass weights for next iteration. All weight/param
// pointers may be generic (global in k_init, shared in k_update).
// ---------------------------------------------------------------------------
__device__ __forceinline__ void prep_slot(
    int b, int s, int t,
    const float* snew, float* lns, float* qv, float* qtv, float* hpart,
    const float* lnsg, const float* lnsb,
    const float* Wq,   const float* Wk,
    const float* lng,  const float* lnb)
{
    ln64_warp(snew, lns, lnsg, lnsb, t);
    __syncthreads();
    {
        int dd = t & 63, h = t >> 6;
        const float4* wr = (const float4*)(Wq + dd * 64) + h * 8;
        const float4* lv = (const float4*)lns + h * 8;
        hpart[t] = dot8x4(lv, wr);
    }
    __syncthreads();
    if (t < 64) qv[t] = (hpart[t] + hpart[t + 64]) * 0.125f;
    __syncthreads();
    {
        int e = t & 63, h = t >> 6;
        float acc = 0.f;
        const float* wk = Wk + (h * 32) * 64 + e;
#pragma unroll 8
        for (int dd = 0; dd < 32; ++dd) acc = fmaf(qv[h * 32 + dd], wk[dd * 64], acc);
        hpart[t] = acc;
    }
    __syncthreads();
    if (t < 64) qtv[t] = hpart[t] + hpart[t + 64];
    __syncthreads();
    if (t < 64) {
        int k = t >> 2, j = t & 3;
        reinterpret_cast<float*>(g_wts4 + b * 128)[(k * 8 + s) * 4 + j] = lng[t] * qtv[t];
    }
    if (t < 32) {
        float p1 = fmaf(lng[t + 32], qtv[t + 32], lng[t] * qtv[t]);
        float p0 = fmaf(lnb[t + 32], qtv[t + 32], lnb[t] * qtv[t]);
#pragma unroll
        for (int off = 16; off; off >>= 1) {
            p1 += __shfl_xor_sync(0xffffffffu, p1, off);
            p0 += __shfl_xor_sync(0xffffffffu, p0, off);
        }
        if (t == 0) { g_c1[b][s] = p1; g_c0[b][s] = p0; }
    }
}

// ---------------------------------------------------------------------------
__global__ void __launch_bounds__(128) k_init(
    const float* __restrict__ noise, const float* __restrict__ mu,
    const float* __restrict__ lsig,
    const float* __restrict__ lnsg, const float* __restrict__ lnsb,
    const float* __restrict__ Wq,   const float* __restrict__ Wk,
    const float* __restrict__ lng,  const float* __restrict__ lnb)
{
    __shared__ __align__(16) float snew[64], lns[64], qv[64], qtv[64], hpart[128];
    int bs = blockIdx.x, b = bs >> 3, s = bs & 7, t = threadIdx.x;
    if (t < 64) {
        int idx = s * 64 + t;
        float v = fmaf(__expf(lsig[idx]), noise[b * 512 + idx], mu[idx]);
        snew[t] = v;
        g_slots[b * 512 + idx] = v;
    }
    __syncthreads();
    prep_slot(b, s, t, snew, lns, qv, qtv, hpart, lnsg, lnsb, Wq, Wk, lng, lnb);
}

// ---------------------------------------------------------------------------
// stage one 32-row warp-tile (8KB) via cp.async (lane l issues 16 x 16B)
// ---------------------------------------------------------------------------
__device__ __forceinline__ void stage_tile(const float4* __restrict__ gsrc,
                                           unsigned sdst, int l)
{
#pragma unroll
    for (int j = 0; j < 16; ++j) {
        int flat = j * 32 + l;
        int row = flat >> 4, k = flat & 15;
        unsigned dst = sdst + (unsigned)((row * 16 + (k ^ (row & 15))) * 16);
        CPA(dst, gsrc + flat);
    }
    CPCOMMIT();
}

// ---------------------------------------------------------------------------
// the big fused pass (round-6 architecture). dynamic smem (float4 units):
//   [0,4096)    xs   : 4 warps x 2 ring x 512 (64KB)
//   [4096,4352) as4  : 4 warps x 64 (4KB)
//   [4352,4480) wts  : 128 (2KB)
//   tail floats: c0s[8], c1s[8], redSg[4][8], redSb[4][8]
// ---------------------------------------------------------------------------
__global__ void __launch_bounds__(PASS_THREADS) k_pass(const float4* __restrict__ x4)
{
    extern __shared__ __align__(16) float4 smem[];
    float4* xs   = smem;
    float4* as4  = smem + 4096;
    float4* wts  = smem + 4352;
    float*  tail = (float*)(smem + 4480);   // 80 floats

    const int b = blockIdx.y;
    const int t = threadIdx.x;
    const int w = t >> 5, l = t & 31;

    unsigned smem_u32;
    { size_t a = __cvta_generic_to_shared(xs); smem_u32 = (unsigned)a; }
    const unsigned xs_base = smem_u32 + (unsigned)(w * 1024 * 16);

    // prologue: prefetch warp-tiles 0 and 1
    const float4* gwarp = x4 + ((size_t)b * NN + (size_t)blockIdx.x * 512 + w * 128) * 16;
    stage_tile(gwarp,       xs_base,        l);
    stage_tile(gwarp + 512, xs_base + 8192, l);

    wts[t] = g_wts4[b * 128 + t];
    if (t < 8)  tail[t]     = g_c0[b][t];
    if (t >= 8 && t < 16) tail[t] = g_c1[b][t - 8];
    __syncthreads();

    float c0r[8], c1r[8], gacc[8], bacc[8];
    ull p2[8];
#pragma unroll
    for (int s = 0; s < 8; ++s) {
        c0r[s] = tail[s]; c1r[s] = tail[8 + s];
        gacc[s] = 0.f; bacc[s] = 0.f; p2[s] = 0ULL;
    }

    const ulonglong2* wt2 = reinterpret_cast<const ulonglong2*>(wts);
    float4* as4w = as4 + w * 64;
    const int g2 = l >> 4, e4 = l & 15;

#pragma unroll
    for (int tl = 0; tl < WTILES; ++tl) {
        if (tl == WTILES - 1) { WAITG(0); }
        else                  { WAITG(1); }
        __syncwarp();

        const ulonglong2* xs2w = reinterpret_cast<const ulonglong2*>(
            xs + w * 1024 + (tl & 1) * 512);

        // ---- phase 1: lane l owns row l of this 32-row tile ----
        {
            ull d2[8];
#pragma unroll
            for (int s = 0; s < 8; ++s) d2[s] = 0ULL;
            ull sum2 = 0ULL, sqa = 0ULL, sqb = 0ULL;
            const int rb = l * 16, ro = l & 15;
#pragma unroll
            for (int k = 0; k < 16; ++k) {
                ulonglong2 v = xs2w[rb + (k ^ ro)];
                ull tv; F2ADD(tv, v.x, v.y); F2ADD(sum2, sum2, tv);
                F2FMA(sqa, v.x, v.x);
                F2FMA(sqb, v.y, v.y);
#pragma unroll
                for (int s = 0; s < 8; ++s) {
                    ulonglong2 wv = wt2[k * 8 + s];
                    F2FMA(d2[s], v.x, wv.x);
                    F2FMA(d2[s], v.y, wv.y);
                }
            }
            float slo, shi; F2UNPK(slo, shi, sum2);
            float sum = slo + shi;
            float qa0, qa1, qb0, qb1;
            F2UNPK(qa0, qa1, sqa); F2UNPK(qb0, qb1, sqb);
            float sq = (qa0 + qa1) + (qb0 + qb1);
            float m    = sum * (1.f / 64.f);
            float istd = rsqrtf(fmaf(sq, 1.f / 64.f, -m * m) + 1e-5f);
            float lo[8], mx = -3.4e38f;
#pragma unroll
            for (int s = 0; s < 8; ++s) {
                float dlo, dhi; F2UNPK(dlo, dhi, d2[s]);
                float d = dlo + dhi;
                lo[s] = fmaf(istd, fmaf(-m, c1r[s], d), c0r[s]);
                mx = fmaxf(mx, lo[s]);
            }
            float pr[8], ps = 0.f;
#pragma unroll
            for (int s = 0; s < 8; ++s) { pr[s] = __expf(lo[s] - mx); ps += pr[s]; }
            float rc  = 1.f / ps;
            float tmi = m * istd;
            float al[8];
#pragma unroll
            for (int s = 0; s < 8; ++s) {
                float a = fmaf(pr[s], rc, 1e-8f);   // softmax + EPS
                gacc[s] += a;
                bacc[s] = fmaf(a, tmi, bacc[s]);
                al[s]   = a * istd;
            }
            as4w[l * 2 + 0] = make_float4(al[0], al[1], al[2], al[3]);
            as4w[l * 2 + 1] = make_float4(al[4], al[5], al[6], al[7]);
        }
        __syncwarp();

        // ---- phase 2: lane (g2, e4) owns slots 4g2..4g2+3 x elems 4e4..4e4+3 ----
#pragma unroll 4
        for (int r = 0; r < 32; ++r) {
            float4 av = as4w[r * 2 + g2];
            ulonglong2 xq = xs2w[r * 16 + (e4 ^ (r & 15))];
            ull a0, a1, a2, a3;
            F2PACK(a0, av.x, av.x); F2PACK(a1, av.y, av.y);
            F2PACK(a2, av.z, av.z); F2PACK(a3, av.w, av.w);
            F2FMA(p2[0], xq.x, a0); F2FMA(p2[1], xq.y, a0);
            F2FMA(p2[2], xq.x, a1); F2FMA(p2[3], xq.y, a1);
            F2FMA(p2[4], xq.x, a2); F2FMA(p2[5], xq.y, a2);
            F2FMA(p2[6], xq.x, a3); F2FMA(p2[7], xq.y, a3);
        }
        __syncwarp();

        if (tl < WTILES - 2)
            stage_tile(gwarp + (tl + 2) * 512, xs_base + (tl & 1) * 8192, l);
    }

    // ---- Sg/Sb warp reduce ----
#pragma unroll
    for (int s = 0; s < 8; ++s) {
        float gv = gacc[s], bv = bacc[s];
#pragma unroll
        for (int off = 16; off; off >>= 1) {
            gv += __shfl_xor_sync(0xffffffffu, gv, off);
            bv += __shfl_xor_sync(0xffffffffu, bv, off);
        }
        if (l == 0) { tail[16 + w * 8 + s] = gv; tail[48 + w * 8 + s] = bv; }
    }
    __syncthreads();   // all warps done; xs reusable as reduction scratch

    // ---- cross-warp Pacc reduce (fixed order) ----
    float4* red4 = xs;   // [w][128] float4 = [w][s*16+e4]
#pragma unroll
    for (int ss = 0; ss < 4; ++ss) {
        float x0, x1, x2, x3;
        F2UNPK(x0, x1, p2[2 * ss]);
        F2UNPK(x2, x3, p2[2 * ss + 1]);
        red4[w * 128 + (4 * g2 + ss) * 16 + e4] = make_float4(x0, x1, x2, x3);
    }
    __syncthreads();

    float4* gp4 = g_part4 + ((size_t)(b * NBLKX + blockIdx.x)) * 132;
    {
        float4 a = red4[t], bb2 = red4[128 + t], c = red4[256 + t], d = red4[384 + t];
        float4 o;
        o.x = ((a.x + bb2.x) + c.x) + d.x;
        o.y = ((a.y + bb2.y) + c.y) + d.y;
        o.z = ((a.z + bb2.z) + c.z) + d.z;
        o.w = ((a.w + bb2.w) + c.w) + d.w;
        gp4[t] = o;
    }
    if (t < 16) {
        const float* src = tail + 16 + (t >= 8 ? 32 : 0) + (t & 7);
        float v = ((src[0] + src[8]) + src[16]) + src[24];
        reinterpret_cast<float*>(gp4)[512 + (t >= 8 ? 8 : 0) + (t & 7)] = v;
    }
}

// ---------------------------------------------------------------------------
// slot update: 128 blocks, each stages all weights into smem and processes
// two (b,s) pairs: (b0, s) and (b0+16, s).
// smem layout (float4 units):
//   0      sWv   1024      7168  sW1  2048      13312 params (240)
//   1024   sWih  3072      9216  sW2  2048      13552 activations (400)
//   4096   sWhh  3072      11264 sWq  1024
//                          12288 sWk  1024
// ---------------------------------------------------------------------------
__global__ void __launch_bounds__(128) k_update(
    const float* __restrict__ lng,  const float* __restrict__ lnb,
    const float* __restrict__ lnsg, const float* __restrict__ lnsb,
    const float* __restrict__ lnmg, const float* __restrict__ lnmb,
    const float* __restrict__ Wq,   const float* __restrict__ Wk,
    const float* __restrict__ Wv,
    const float* __restrict__ W_ih, const float* __restrict__ W_hh,
    const float* __restrict__ b_ih, const float* __restrict__ b_hh,
    const float* __restrict__ W1,   const float* __restrict__ b1,
    const float* __restrict__ W2,   const float* __restrict__ b2,
    float* __restrict__ out, int last)
{
    extern __shared__ __align__(16) float4 smu[];
    float4* sWv  = smu;
    float4* sWih = smu + 1024;
    float4* sWhh = smu + 4096;
    float4* sW1  = smu + 7168;
    float4* sW2  = smu + 9216;
    float4* sWq  = smu + 11264;
    float4* sWk  = smu + 12288;
    float*  sPar = (float*)(smu + 13312);
    float*  sAct = (float*)(smu + 13552);

    float *P = sAct, *Uv = sAct + 64, *upds = sAct + 128, *slp = sAct + 192;
    float *updh = sAct + 256, *mln = sAct + 320, *snew = sAct + 384;
    float *lns = sAct + 448, *qv = sAct + 512, *qtv = sAct + 576;
    float *gi = sAct + 640, *gh = sAct + 832, *hhs = sAct + 1024, *hpart = sAct + 1152;
    float4* pg4 = (float4*)(sAct + 1280);   // 64 float4
    float*  sred = sAct + 1536;             // 8
    float*  sS   = sAct + 1544;             // [0]=Sg [1]=Sb

    float *sBih = sPar, *sBhh = sPar + 192, *sB1 = sPar + 384, *sB2 = sPar + 512;
    float *sLng = sPar + 576, *sLnb = sPar + 640, *sLnsg = sPar + 704;
    float *sLnsb = sPar + 768, *sLnmg = sPar + 832, *sLnmb = sPar + 896;

    const int bx = blockIdx.x, b0 = bx >> 3, s = bx & 7, t = threadIdx.x;

    unsigned sb;
    { size_t a = __cvta_generic_to_shared(smu); sb = (unsigned)a; }
    const unsigned parU = sb + 13312u * 16u;

    // ---- G0: Wv + biases + ln params ----
    for (int i = t; i < 1024; i += 128) CPA(sb + i * 16, (const float4*)Wv + i);
    if (t < 48) CPA(parU + t * 16,          (const float4*)b_ih + t);
    if (t < 48) CPA(parU + (48 + t) * 16,   (const float4*)b_hh + t);
    if (t < 32) CPA(parU + (96 + t) * 16,   (const float4*)b1 + t);
    if (t < 16) CPA(parU + (128 + t) * 16,  (const float4*)b2 + t);
    if (t < 16) CPA(parU + (144 + t) * 16,  (const float4*)lng + t);
    if (t < 16) CPA(parU + (160 + t) * 16,  (const float4*)lnb + t);
    if (t < 16) CPA(parU + (176 + t) * 16,  (const float4*)lnsg + t);
    if (t < 16) CPA(parU + (192 + t) * 16,  (const float4*)lnsb + t);
    if (t < 16) CPA(parU + (208 + t) * 16,  (const float4*)lnmg + t);
    if (t < 16) CPA(parU + (224 + t) * 16,  (const float4*)lnmb + t);
    CPCOMMIT();
    // ---- G1: W_ih ----
    for (int i = t; i < 3072; i += 128) CPA(sb + (1024 + i) * 16, (const float4*)W_ih + i);
    CPCOMMIT();
    // ---- G2: W_hh ----
    for (int i = t; i < 3072; i += 128) CPA(sb + (4096 + i) * 16, (const float4*)W_hh + i);
    CPCOMMIT();

#pragma unroll 1
    for (int p = 0; p < 2; ++p) {
        const int b = b0 + 16 * p;

        // ---- A: coalesced fixed-order reduce of 32 records for this slot ----
        const float4* pb4 = g_part4 + (size_t)b * NBLKX * 132;
        if (t < 64) {
            int e4 = t & 15, grp = t >> 4;
            const float4* src = pb4 + (size_t)grp * 8 * 132 + s * 16 + e4;
            float4 acc = make_float4(0.f, 0.f, 0.f, 0.f);
#pragma unroll
            for (int j = 0; j < 8; ++j) {
                float4 v = src[(size_t)j * 132];
                acc.x += v.x; acc.y += v.y; acc.z += v.z; acc.w += v.w;
            }
            pg4[grp * 16 + e4] = acc;
        } else if (t < 72) {
            int which = (t - 64) >> 2;
            int grp = (t - 64) & 3;
            const float* src = reinterpret_cast<const float*>(pb4)
                             + (size_t)grp * 8 * PREC + 512 + which * 8 + s;
            float acc = 0.f;
#pragma unroll
            for (int j = 0; j < 8; ++j) acc += src[(size_t)j * PREC];
            sred[t - 64] = acc;
        }
        if (t >= 64) slp[t - 64] = g_slots[b * 512 + s * 64 + (t - 64)];

        if (p == 0) {
            // ---- G3..G6 (overlap with phase A latency) ----
            for (int i = t; i < 2048; i += 128) CPA(sb + (7168 + i) * 16, (const float4*)W1 + i);
            CPCOMMIT();
            for (int i = t; i < 2048; i += 128) CPA(sb + (9216 + i) * 16, (const float4*)W2 + i);
            CPCOMMIT();
            for (int i = t; i < 1024; i += 128) CPA(sb + (11264 + i) * 16, (const float4*)Wq + i);
            CPCOMMIT();
            for (int i = t; i < 1024; i += 128) CPA(sb + (12288 + i) * 16, (const float4*)Wk + i);
            CPCOMMIT();
        }

        WAITG(6);            // G0 (Wv + params) complete
        __syncthreads();
        if (t < 16) {
            float4 a = pg4[t], bg = pg4[16 + t], c = pg4[32 + t], d = pg4[48 + t];
            float4 o;
            o.x = ((a.x + bg.x) + c.x) + d.x;
            o.y = ((a.y + bg.y) + c.y) + d.y;
            o.z = ((a.z + bg.z) + c.z) + d.z;
            o.w = ((a.w + bg.w) + c.w) + d.w;
            reinterpret_cast<float4*>(P)[t] = o;
        }
        if (t == 0) sS[0] = ((sred[0] + sred[1]) + sred[2]) + sred[3];
        if (t == 1) sS[1] = ((sred[4] + sred[5]) + sred[6]) + sred[7];
        __syncthreads();

        // ---- B: U[e] = (g*(P - Sb) + b*Sg)/Sg ----
        if (t < 64) Uv[t] = fmaf(sLng[t], P[t] - sS[1], sLnb[t] * sS[0]) / sS[0];
        __syncthreads();

        // ---- C: upds = U @ Wv^T (half-split, smem weights) ----
        {
            int dd = t & 63, h = t >> 6;
            float r = dot8x4((const float4*)Uv + h * 8, sWv + dd * 16 + h * 8);
            __syncthreads();
            hpart[t] = r;
        }
        __syncthreads();
        if (t < 64) upds[t] = hpart[t] + hpart[t + 64];
        WAITG(4);            // G1,G2 (W_ih, W_hh) complete
        __syncthreads();

        // ---- D: GRU pre-activations ----
#pragma unroll
        for (int k = 0; k < 3; ++k) {
            int id = t + 128 * k;
            if (id < 192) {
                gi[id] = dot16x4((const float4*)upds, sWih + id * 16, sBih[id]);
            } else {
                int j = id - 192;
                gh[j] = dot16x4((const float4*)slp, sWhh + j * 16, sBhh[j]);
            }
        }
        __syncthreads();

        // ---- E: gates ----
        if (t < 64) {
            float r = sigm(gi[t]      + gh[t]);
            float z = sigm(gi[64 + t] + gh[64 + t]);
            float n = tanhf(fmaf(r, gh[128 + t], gi[128 + t]));
            updh[t] = fmaf(z, slp[t] - n, n);
        }
        __syncthreads();

        // ---- F: LN(updh) ----
        ln64_warp(updh, mln, sLnmg, sLnmb, t);
        WAITG(3);            // W1 complete
        __syncthreads();

        // ---- G: hidden = relu(mln @ W1^T + b1) ----
        hhs[t] = fmaxf(dot16x4((const float4*)mln, sW1 + t * 16, sB1[t]), 0.f);
        WAITG(2);            // W2 complete
        __syncthreads();

        // ---- H: snew = updh + hh @ W2^T + b2 ----
        {
            int dd = t & 63, h = t >> 6;
            float r = dot16x4((const float4*)hhs + h * 16, sW2 + dd * 32 + h * 16, 0.f);
            __syncthreads();
            hpart[t] = r;
        }
        __syncthreads();
        if (t < 64) {
            float v = updh[t] + sB2[t] + (hpart[t] + hpart[t + 64]);
            snew[t] = v;
            g_slots[b * 512 + s * 64 + t] = v;
            if (last) out[b * 512 + s * 64 + t] = v;
        }
        WAITG(0);            // Wq, Wk complete
        __syncthreads();

        if (!last)
            prep_slot(b, s, t, snew, lns, qv, qtv, hpart, sLnsg, sLnsb,
                      (const float*)sWq, (const float*)sWk, sLng, sLnb);
        __syncthreads();     // sAct reuse for second pair
    }
}

// ---------------------------------------------------------------------------
extern "C" void kernel_launch(void* const* d_in, const int* in_sizes, int n_in,
                              void* d_out, int out_size)
{
    const float* x     = (const float*)d_in[0];
    const float* noise = (const float*)d_in[1];
    const float* mu    = (const float*)d_in[2];
    const float* lsig  = (const float*)d_in[3];
    const float* lng   = (const float*)d_in[4];
    const float* lnb   = (const float*)d_in[5];
    const float* lnsg  = (const float*)d_in[6];
    const float* lnsb  = (const float*)d_in[7];
    const float* lnmg  = (const float*)d_in[8];
    const float* lnmb  = (const float*)d_in[9];
    const float* Wq    = (const float*)d_in[10];
    const float* Wk    = (const float*)d_in[11];
    const float* Wv    = (const float*)d_in[12];
    const float* W_ih  = (const float*)d_in[13];
    const float* W_hh  = (const float*)d_in[14];
    const float* b_ih  = (const float*)d_in[15];
    const float* b_hh  = (const float*)d_in[16];
    const float* W1    = (const float*)d_in[17];
    const float* b1    = (const float*)d_in[18];
    const float* W2    = (const float*)d_in[19];
    const float* b2    = (const float*)d_in[20];
    float* out = (float*)d_out;

    cudaFuncSetAttribute(k_pass, cudaFuncAttributeMaxDynamicSharedMemorySize, SMEM_BYTES);
    cudaFuncSetAttribute(k_update, cudaFuncAttributeMaxDynamicSharedMemorySize, UPD_SMEM);

    k_init<<<BB * SS, 128>>>(noise, mu, lsig, lnsg, lnsb, Wq, Wk, lng, lnb);

    for (int it = 0; it < 3; ++it) {
        k_pass<<<dim3(NBLKX, BB), PASS_THREADS, SMEM_BYTES>>>((const float4*)x);
        k_update<<<128, 128, UPD_SMEM>>>(lng, lnb, lnsg, lnsb, lnmg, lnmb,
                                         Wq, Wk, Wv, W_ih, W_hh, b_ih, b_hh,
                                         W1, b1, W2, b2, out, it == 2);
    }
}

// round 12
// speedup vs baseline: 1.1132x; 1.0674x over previous
#include <cuda_runtime.h>

// ---------------------------------------------------------------------------
// SlotAttention fused. B=32, N=16384, S=8, D=64, H=128, ITERS=3.
// k_pass: per-warp cp.async ring-2, PAIRED phase-1 (both buffers share each
//         wts broadcast load), folded-LN logits + softmax + rank-1 accum,
//         f32x2 FMAs, no block syncs in mainloop.
// k_update: 128 blocks; stages all weights into 223KB smem via cp.async and
//         runs the slot-update chain for two (b,s) pairs.
// ---------------------------------------------------------------------------

#define BB 32
#define NN 16384
#define SS 8
#define DD 64
#define HH 128
#define NBLKX 32                 // pass blocks per batch (512 rows each)
#define PREC 528                 // floats per record: 512 Pacc + 8 Sg + 8 Sb
#define PASS_THREADS 128
// k_pass smem: xs 4096f4 + as4 512f4 + wts 128f4 + tail 80f = 76096 -> 76160
#define SMEM_BYTES 76160
#define UPD_SMEM (13952 * 16)    // k_update smem: 223232 bytes

typedef unsigned long long ull;

__device__ float  g_slots[BB * SS * DD];
__device__ float4 g_wts4[BB * 128];          // [b][k=0..15][s=0..7]
__device__ float  g_c0[BB][SS];
__device__ float  g_c1[BB][SS];
__device__ float4 g_part4[(size_t)BB * NBLKX * 132];

#define F2FMA(d, a, b) asm("fma.rn.f32x2 %0, %1, %2, %0;" : "+l"(d) : "l"(a), "l"(b))
#define F2ADD(d, a, b) asm("add.rn.f32x2 %0, %1, %2;" : "=l"(d) : "l"(a), "l"(b))
#define F2PACK(v, lo, hi) asm("mov.b64 %0, {%1, %2};" : "=l"(v) : "f"(lo), "f"(hi))
#define F2UNPK(lo, hi, v) asm("mov.b64 {%0, %1}, %2;" : "=f"(lo), "=f"(hi) : "l"(v))

#define CPA(dst, src) asm volatile("cp.async.cg.shared.global [%0], [%1], 16;" \
                                   :: "r"(dst), "l"(src))
#define CPCOMMIT() asm volatile("cp.async.commit_group;")
#define WAITG(n) asm volatile("cp.async.wait_group " #n ";" ::: "memory")

__device__ __forceinline__ float sigm(float x) { return 1.f / (1.f + __expf(-x)); }

__device__ __forceinline__ float dot16x4(const float4* a, const float4* w, float bias) {
    float a0 = 0.f, a1 = 0.f, a2 = 0.f, a3 = 0.f;
#pragma unroll
    for (int e = 0; e < 4; ++e) {
        float4 x0 = a[e],      w0 = w[e];
        float4 x1 = a[e + 4],  w1 = w[e + 4];
        float4 x2 = a[e + 8],  w2 = w[e + 8];
        float4 x3 = a[e + 12], w3 = w[e + 12];
        a0 = fmaf(x0.x, w0.x, fmaf(x0.y, w0.y, fmaf(x0.z, w0.z, fmaf(x0.w, w0.w, a0))));
        a1 = fmaf(x1.x, w1.x, fmaf(x1.y, w1.y, fmaf(x1.z, w1.z, fmaf(x1.w, w1.w, a1))));
        a2 = fmaf(x2.x, w2.x, fmaf(x2.y, w2.y, fmaf(x2.z, w2.z, fmaf(x2.w, w2.w, a2))));
        a3 = fmaf(x3.x, w3.x, fmaf(x3.y, w3.y, fmaf(x3.z, w3.z, fmaf(x3.w, w3.w, a3))));
    }
    return bias + ((a0 + a1) + (a2 + a3));
}
__device__ __forceinline__ float dot8x4(const float4* a, const float4* w) {
    float a0 = 0.f, a1 = 0.f;
#pragma unroll
    for (int e = 0; e < 4; ++e) {
        float4 x0 = a[e],     w0 = w[e];
        float4 x1 = a[e + 4], w1 = w[e + 4];
        a0 = fmaf(x0.x, w0.x, fmaf(x0.y, w0.y, fmaf(x0.z, w0.z, fmaf(x0.w, w0.w, a0))));
        a1 = fmaf(x1.x, w1.x, fmaf(x1.y, w1.y, fmaf(x1.z, w1.z, fmaf(x1.w, w1.w, a1))));
    }
    return a0 + a1;
}

__device__ __forceinline__ void ln64_warp(const float* in, float* out,
                                          const float* g,
                                          const float* bt, int t) {
    if (t < 32) {
        float v0 = in[t], v1 = in[t + 32];
        float sum = v0 + v1;
        float sq  = fmaf(v0, v0, v1 * v1);
#pragma unroll
        for (int off = 16; off; off >>= 1) {
            sum += __shfl_xor_sync(0xffffffffu, sum, off);
            sq  += __shfl_xor_sync(0xffffffffu, sq,  off);
        }
        float m    = sum * (1.f / 64.f);
        float istd = rsqrtf(fmaf(sq, 1.f / 64.f, -m * m) + 1e-5f);
        out[t]      = fmaf((v0 - m) * istd, g[t],      bt[t]);
        out[t + 32] = fmaf((v1 - m) * istd, g[t + 32], bt[t + 32]);
    }
}

// ---------------------------------------------------------------------------
__device__ __forceinline__ void prep_slot(
    int b, int s, int t,
    const float* snew, float* lns, float* qv, float* qtv, float* hpart,
    const float* lnsg, const float* lnsb,
    const float* Wq,   const float* Wk,
    const float* lng,  const float* lnb)
{
    ln64_warp(snew, lns, lnsg, lnsb, t);
    __syncthreads();
    {
        int dd = t & 63, h = t >> 6;
        const float4* wr = (const float4*)(Wq + dd * 64) + h * 8;
        const float4* lv = (const float4*)lns + h * 8;
        hpart[t] = dot8x4(lv, wr);
    }
    __syncthreads();
    if (t < 64) qv[t] = (hpart[t] + hpart[t + 64]) * 0.125f;
    __syncthreads();
    {
        int e = t & 63, h = t >> 6;
        float acc = 0.f;
        const float* wk = Wk + (h * 32) * 64 + e;
#pragma unroll 8
        for (int dd = 0; dd < 32; ++dd) acc = fmaf(qv[h * 32 + dd], wk[dd * 64], acc);
        hpart[t] = acc;
    }
    __syncthreads();
    if (t < 64) qtv[t] = hpart[t] + hpart[t + 64];
    __syncthreads();
    if (t < 64) {
        int k = t >> 2, j = t & 3;
        reinterpret_cast<float*>(g_wts4 + b * 128)[(k * 8 + s) * 4 + j] = lng[t] * qtv[t];
    }
    if (t < 32) {
        float p1 = fmaf(lng[t + 32], qtv[t + 32], lng[t] * qtv[t]);
        float p0 = fmaf(lnb[t + 32], qtv[t + 32], lnb[t] * qtv[t]);
#pragma unroll
        for (int off = 16; off; off >>= 1) {
            p1 += __shfl_xor_sync(0xffffffffu, p1, off);
            p0 += __shfl_xor_sync(0xffffffffu, p0, off);
        }
        if (t == 0) { g_c1[b][s] = p1; g_c0[b][s] = p0; }
    }
}

// ---------------------------------------------------------------------------
__global__ void __launch_bounds__(128) k_init(
    const float* __restrict__ noise, const float* __restrict__ mu,
    const float* __restrict__ lsig,
    const float* __restrict__ lnsg, const float* __restrict__ lnsb,
    const float* __restrict__ Wq,   const float* __restrict__ Wk,
    const float* __restrict__ lng,  const float* __restrict__ lnb)
{
    __shared__ __align__(16) float snew[64], lns[64], qv[64], qtv[64], hpart[128];
    int bs = blockIdx.x, b = bs >> 3, s = bs & 7, t = threadIdx.x;
    if (t < 64) {
        int idx = s * 64 + t;
        float v = fmaf(__expf(lsig[idx]), noise[b * 512 + idx], mu[idx]);
        snew[t] = v;
        g_slots[b * 512 + idx] = v;
    }
    __syncthreads();
    prep_slot(b, s, t, snew, lns, qv, qtv, hpart, lnsg, lnsb, Wq, Wk, lng, lnb);
}

// ---------------------------------------------------------------------------
__device__ __forceinline__ void stage_tile(const float4* __restrict__ gsrc,
                                           unsigned sdst, int l)
{
#pragma unroll
    for (int j = 0; j < 16; ++j) {
        int flat = j * 32 + l;
        int row = flat >> 4, k = flat & 15;
        unsigned dst = sdst + (unsigned)((row * 16 + (k ^ (row & 15))) * 16);
        CPA(dst, gsrc + flat);
    }
    CPCOMMIT();
}

// phase-1 epilogue: stats -> softmax -> alphas; accumulates Sg/Sb partials
__device__ __forceinline__ void p1_epilogue(
    const ull* d2, ull sum2, ull sqa, ull sqb,
    const float* c0r, const float* c1r,
    float* gacc, float* bacc, float4* dst, int l)
{
    float slo, shi; F2UNPK(slo, shi, sum2);
    float sum = slo + shi;
    float qa0, qa1, qb0, qb1;
    F2UNPK(qa0, qa1, sqa); F2UNPK(qb0, qb1, sqb);
    float sq = (qa0 + qa1) + (qb0 + qb1);
    float m    = sum * (1.f / 64.f);
    float istd = rsqrtf(fmaf(sq, 1.f / 64.f, -m * m) + 1e-5f);
    float lo[8], mx = -3.4e38f;
#pragma unroll
    for (int s = 0; s < 8; ++s) {
        float dlo, dhi; F2UNPK(dlo, dhi, d2[s]);
        float d = dlo + dhi;
        lo[s] = fmaf(istd, fmaf(-m, c1r[s], d), c0r[s]);
        mx = fmaxf(mx, lo[s]);
    }
    float pr[8], ps = 0.f;
#pragma unroll
    for (int s = 0; s < 8; ++s) { pr[s] = __expf(lo[s] - mx); ps += pr[s]; }
    float rc  = 1.f / ps;
    float tmi = m * istd;
    float al[8];
#pragma unroll
    for (int s = 0; s < 8; ++s) {
        float a = fmaf(pr[s], rc, 1e-8f);   // softmax + EPS
        gacc[s] += a;
        bacc[s] = fmaf(a, tmi, bacc[s]);
        al[s]   = a * istd;
    }
    dst[l * 2 + 0] = make_float4(al[0], al[1], al[2], al[3]);
    dst[l * 2 + 1] = make_float4(al[4], al[5], al[6], al[7]);
}

// phase-2 rank-1 accumulation over one 32-row tile
__device__ __forceinline__ void p2_accum(
    const ulonglong2* xs2w, const float4* as4t, ull* p2, int g2, int e4)
{
#pragma unroll 4
    for (int r = 0; r < 32; ++r) {
        float4 av = as4t[r * 2 + g2];
        ulonglong2 xq = xs2w[r * 16 + (e4 ^ (r & 15))];
        ull a0, a1, a2, a3;
        F2PACK(a0, av.x, av.x); F2PACK(a1, av.y, av.y);
        F2PACK(a2, av.z, av.z); F2PACK(a3, av.w, av.w);
        F2FMA(p2[0], xq.x, a0); F2FMA(p2[1], xq.y, a0);
        F2FMA(p2[2], xq.x, a1); F2FMA(p2[3], xq.y, a1);
        F2FMA(p2[4], xq.x, a2); F2FMA(p2[5], xq.y, a2);
        F2FMA(p2[6], xq.x, a3); F2FMA(p2[7], xq.y, a3);
    }
}

// ---------------------------------------------------------------------------
// the big fused pass, paired phase-1. dynamic smem (float4 units):
//   [0,4096)    xs   : 4 warps x 2 ring x 512 (64KB)
//   [4096,4608) as4  : 4 warps x 2 tiles x 64 (8KB)
//   [4608,4736) wts  : 128 (2KB)
//   tail floats: c0s[8], c1s[8], redSg[4][8], redSb[4][8]
// ---------------------------------------------------------------------------
__global__ void __launch_bounds__(PASS_THREADS, 3) k_pass(const float4* __restrict__ x4)
{
    extern __shared__ __align__(16) float4 smem[];
    float4* xs   = smem;
    float4* as4  = smem + 4096;
    float4* wts  = smem + 4608;
    float*  tail = (float*)(smem + 4736);   // 80 floats

    const int b = blockIdx.y;
    const int t = threadIdx.x;
    const int w = t >> 5, l = t & 31;

    unsigned smem_u32;
    { size_t a = __cvta_generic_to_shared(xs); smem_u32 = (unsigned)a; }
    const unsigned xs_base = smem_u32 + (unsigned)(w * 1024 * 16);

    const float4* gwarp = x4 + ((size_t)b * NN + (size_t)blockIdx.x * 512 + w * 128) * 16;
    stage_tile(gwarp,       xs_base,        l);   // t0 -> buf0
    stage_tile(gwarp + 512, xs_base + 8192, l);   // t1 -> buf1

    wts[t] = g_wts4[b * 128 + t];
    if (t < 8)  tail[t]     = g_c0[b][t];
    if (t >= 8 && t < 16) tail[t] = g_c1[b][t - 8];
    __syncthreads();

    float c0r[8], c1r[8], gacc[8], bacc[8];
    ull p2[8];
#pragma unroll
    for (int s = 0; s < 8; ++s) {
        c0r[s] = tail[s]; c1r[s] = tail[8 + s];
        gacc[s] = 0.f; bacc[s] = 0.f; p2[s] = 0ULL;
    }

    const ulonglong2* wt2 = reinterpret_cast<const ulonglong2*>(wts);
    float4* as4w = as4 + w * 128;          // 2 tiles x 64
    const int g2 = l >> 4, e4 = l & 15;
    const ulonglong2* xsA = reinterpret_cast<const ulonglong2*>(xs + w * 1024);
    const ulonglong2* xsB = reinterpret_cast<const ulonglong2*>(xs + w * 1024 + 512);

#pragma unroll
    for (int pr = 0; pr < 2; ++pr) {
        WAITG(0);
        __syncwarp();

        // ---- phase 1 (paired): lane l owns row l of BOTH buffers;
        //      each wts broadcast serves both tiles ----
        {
            ull dA[8], dB[8];
#pragma unroll
            for (int s = 0; s < 8; ++s) { dA[s] = 0ULL; dB[s] = 0ULL; }
            ull sumA = 0ULL, sumB = 0ULL, sqaA = 0ULL, sqaB = 0ULL, sqbA = 0ULL, sqbB = 0ULL;
            const int rb = l * 16, ro = l & 15;
#pragma unroll
            for (int k = 0; k < 16; ++k) {
                ulonglong2 vA = xsA[rb + (k ^ ro)];
                ulonglong2 vB = xsB[rb + (k ^ ro)];
                ull tv;
                F2ADD(tv, vA.x, vA.y); F2ADD(sumA, sumA, tv);
                F2ADD(tv, vB.x, vB.y); F2ADD(sumB, sumB, tv);
                F2FMA(sqaA, vA.x, vA.x); F2FMA(sqbA, vA.y, vA.y);
                F2FMA(sqaB, vB.x, vB.x); F2FMA(sqbB, vB.y, vB.y);
#pragma unroll
                for (int s = 0; s < 8; ++s) {
                    ulonglong2 wv = wt2[k * 8 + s];
                    F2FMA(dA[s], vA.x, wv.x); F2FMA(dA[s], vA.y, wv.y);
                    F2FMA(dB[s], vB.x, wv.x); F2FMA(dB[s], vB.y, wv.y);
                }
            }
            p1_epilogue(dA, sumA, sqaA, sqbA, c0r, c1r, gacc, bacc, as4w,      l);
            p1_epilogue(dB, sumB, sqaB, sqbB, c0r, c1r, gacc, bacc, as4w + 64, l);
        }
        __syncwarp();

        // ---- phase 2 tile A, then restage buf0; tile B, restage buf1 ----
        p2_accum(xsA, as4w, p2, g2, e4);
        if (pr == 0) stage_tile(gwarp + 2 * 512, xs_base, l);        // t2 -> buf0
        p2_accum(xsB, as4w + 64, p2, g2, e4);
        if (pr == 0) stage_tile(gwarp + 3 * 512, xs_base + 8192, l); // t3 -> buf1
        __syncwarp();
    }

    // ---- Sg/Sb warp reduce ----
#pragma unroll
    for (int s = 0; s < 8; ++s) {
        float gv = gacc[s], bv = bacc[s];
#pragma unroll
        for (int off = 16; off; off >>= 1) {
            gv += __shfl_xor_sync(0xffffffffu, gv, off);
            bv += __shfl_xor_sync(0xffffffffu, bv, off);
        }
        if (l == 0) { tail[16 + w * 8 + s] = gv; tail[48 + w * 8 + s] = bv; }
    }
    __syncthreads();   // all warps done; xs reusable as reduction scratch

    // ---- cross-warp Pacc reduce (fixed order) ----
    float4* red4 = xs;   // [w][128] float4 = [w][s*16+e4]
#pragma unroll
    for (int ss = 0; ss < 4; ++ss) {
        float x0, x1, x2, x3;
        F2UNPK(x0, x1, p2[2 * ss]);
        F2UNPK(x2, x3, p2[2 * ss + 1]);
        red4[w * 128 + (4 * g2 + ss) * 16 + e4] = make_float4(x0, x1, x2, x3);
    }
    __syncthreads();

    float4* gp4 = g_part4 + ((size_t)(b * NBLKX + blockIdx.x)) * 132;
    {
        float4 a = red4[t], bb2 = red4[128 + t], c = red4[256 + t], d = red4[384 + t];
        float4 o;
        o.x = ((a.x + bb2.x) + c.x) + d.x;
        o.y = ((a.y + bb2.y) + c.y) + d.y;
        o.z = ((a.z + bb2.z) + c.z) + d.z;
        o.w = ((a.w + bb2.w) + c.w) + d.w;
        gp4[t] = o;
    }
    if (t < 16) {
        const float* src = tail + 16 + (t >= 8 ? 32 : 0) + (t & 7);
        float v = ((src[0] + src[8]) + src[16]) + src[24];
        reinterpret_cast<float*>(gp4)[512 + (t >= 8 ? 8 : 0) + (t & 7)] = v;
    }
}

// ---------------------------------------------------------------------------
// slot update: 128 blocks, weights staged to smem, two (b,s) pairs per block
// ---------------------------------------------------------------------------
__global__ void __launch_bounds__(128) k_update(
    const float* __restrict__ lng,  const float* __restrict__ lnb,
    const float* __restrict__ lnsg, const float* __restrict__ lnsb,
    const float* __restrict__ lnmg, const float* __restrict__ lnmb,
    const float* __restrict__ Wq,   const float* __restrict__ Wk,
    const float* __restrict__ Wv,
    const float* __restrict__ W_ih, const float* __restrict__ W_hh,
    const float* __restrict__ b_ih, const float* __restrict__ b_hh,
    const float* __restrict__ W1,   const float* __restrict__ b1,
    const float* __restrict__ W2,   const float* __restrict__ b2,
    float* __restrict__ out, int last)
{
    extern __shared__ __align__(16) float4 smu[];
    float4* sWv  = smu;
    float4* sWih = smu + 1024;
    float4* sWhh = smu + 4096;
    float4* sW1  = smu + 7168;
    float4* sW2  = smu + 9216;
    float4* sWq  = smu + 11264;
    float4* sWk  = smu + 12288;
    float*  sPar = (float*)(smu + 13312);
    float*  sAct = (float*)(smu + 13552);

    float *P = sAct, *Uv = sAct + 64, *upds = sAct + 128, *slp = sAct + 192;
    float *updh = sAct + 256, *mln = sAct + 320, *snew = sAct + 384;
    float *lns = sAct + 448, *qv = sAct + 512, *qtv = sAct + 576;
    float *gi = sAct + 640, *gh = sAct + 832, *hhs = sAct + 1024, *hpart = sAct + 1152;
    float4* pg4 = (float4*)(sAct + 1280);
    float*  sred = sAct + 1536;
    float*  sS   = sAct + 1544;

    float *sBih = sPar, *sBhh = sPar + 192, *sB1 = sPar + 384, *sB2 = sPar + 512;
    float *sLng = sPar + 576, *sLnb = sPar + 640, *sLnsg = sPar + 704;
    float *sLnsb = sPar + 768, *sLnmg = sPar + 832, *sLnmb = sPar + 896;

    const int bx = blockIdx.x, b0 = bx >> 3, s = bx & 7, t = threadIdx.x;

    unsigned sb;
    { size_t a = __cvta_generic_to_shared(smu); sb = (unsigned)a; }
    const unsigned parU = sb + 13312u * 16u;

    for (int i = t; i < 1024; i += 128) CPA(sb + i * 16, (const float4*)Wv + i);
    if (t < 48) CPA(parU + t * 16,          (const float4*)b_ih + t);
    if (t < 48) CPA(parU + (48 + t) * 16,   (const float4*)b_hh + t);
    if (t < 32) CPA(parU + (96 + t) * 16,   (const float4*)b1 + t);
    if (t < 16) CPA(parU + (128 + t) * 16,  (const float4*)b2 + t);
    if (t < 16) CPA(parU + (144 + t) * 16,  (const float4*)lng + t);
    if (t < 16) CPA(parU + (160 + t) * 16,  (const float4*)lnb + t);
    if (t < 16) CPA(parU + (176 + t) * 16,  (const float4*)lnsg + t);
    if (t < 16) CPA(parU + (192 + t) * 16,  (const float4*)lnsb + t);
    if (t < 16) CPA(parU + (208 + t) * 16,  (const float4*)lnmg + t);
    if (t < 16) CPA(parU + (224 + t) * 16,  (const float4*)lnmb + t);
    CPCOMMIT();
    for (int i = t; i < 3072; i += 128) CPA(sb + (1024 + i) * 16, (const float4*)W_ih + i);
    CPCOMMIT();
    for (int i = t; i < 3072; i += 128) CPA(sb + (4096 + i) * 16, (const float4*)W_hh + i);
    CPCOMMIT();

#pragma unroll 1
    for (int p = 0; p < 2; ++p) {
        const int b = b0 + 16 * p;

        const float4* pb4 = g_part4 + (size_t)b * NBLKX * 132;
        if (t < 64) {
            int e4 = t & 15, grp = t >> 4;
            const float4* src = pb4 + (size_t)grp * 8 * 132 + s * 16 + e4;
            float4 acc = make_float4(0.f, 0.f, 0.f, 0.f);
#pragma unroll
            for (int j = 0; j < 8; ++j) {
                float4 v = src[(size_t)j * 132];
                acc.x += v.x; acc.y += v.y; acc.z += v.z; acc.w += v.w;
            }
            pg4[grp * 16 + e4] = acc;
        } else if (t < 72) {
            int which = (t - 64) >> 2;
            int grp = (t - 64) & 3;
            const float* src = reinterpret_cast<const float*>(pb4)
                             + (size_t)grp * 8 * PREC + 512 + which * 8 + s;
            float acc = 0.f;
#pragma unroll
            for (int j = 0; j < 8; ++j) acc += src[(size_t)j * PREC];
            sred[t - 64] = acc;
        }
        if (t >= 64) slp[t - 64] = g_slots[b * 512 + s * 64 + (t - 64)];

        if (p == 0) {
            for (int i = t; i < 2048; i += 128) CPA(sb + (7168 + i) * 16, (const float4*)W1 + i);
            CPCOMMIT();
            for (int i = t; i < 2048; i += 128) CPA(sb + (9216 + i) * 16, (const float4*)W2 + i);
            CPCOMMIT();
            for (int i = t; i < 1024; i += 128) CPA(sb + (11264 + i) * 16, (const float4*)Wq + i);
            CPCOMMIT();
            for (int i = t; i < 1024; i += 128) CPA(sb + (12288 + i) * 16, (const float4*)Wk + i);
            CPCOMMIT();
        }

        WAITG(6);
        __syncthreads();
        if (t < 16) {
            float4 a = pg4[t], bg = pg4[16 + t], c = pg4[32 + t], d = pg4[48 + t];
            float4 o;
            o.x = ((a.x + bg.x) + c.x) + d.x;
            o.y = ((a.y + bg.y) + c.y) + d.y;
            o.z = ((a.z + bg.z) + c.z) + d.z;
            o.w = ((a.w + bg.w) + c.w) + d.w;
            reinterpret_cast<float4*>(P)[t] = o;
        }
        if (t == 0) sS[0] = ((sred[0] + sred[1]) + sred[2]) + sred[3];
        if (t == 1) sS[1] = ((sred[4] + sred[5]) + sred[6]) + sred[7];
        __syncthreads();

        if (t < 64) Uv[t] = fmaf(sLng[t], P[t] - sS[1], sLnb[t] * sS[0]) / sS[0];
        __syncthreads();

        {
            int dd = t & 63, h = t >> 6;
            float r = dot8x4((const float4*)Uv + h * 8, sWv + dd * 16 + h * 8);
            __syncthreads();
            hpart[t] = r;
        }
        __syncthreads();
        if (t < 64) upds[t] = hpart[t] + hpart[t + 64];
        WAITG(4);
        __syncthreads();

#pragma unroll
        for (int k = 0; k < 3; ++k) {
            int id = t + 128 * k;
            if (id < 192) {
                gi[id] = dot16x4((const float4*)upds, sWih + id * 16, sBih[id]);
            } else {
                int j = id - 192;
                gh[j] = dot16x4((const float4*)slp, sWhh + j * 16, sBhh[j]);
            }
        }
        __syncthreads();

        if (t < 64) {
            float r = sigm(gi[t]      + gh[t]);
            float z = sigm(gi[64 + t] + gh[64 + t]);
            float n = tanhf(fmaf(r, gh[128 + t], gi[128 + t]));
            updh[t] = fmaf(z, slp[t] - n, n);
        }
        __syncthreads();

        ln64_warp(updh, mln, sLnmg, sLnmb, t);
        WAITG(3);
        __syncthreads();

        hhs[t] = fmaxf(dot16x4((const float4*)mln, sW1 + t * 16, sB1[t]), 0.f);
        WAITG(2);
        __syncthreads();

        {
            int dd = t & 63, h = t >> 6;
            float r = dot16x4((const float4*)hhs + h * 16, sW2 + dd * 32 + h * 16, 0.f);
            __syncthreads();
            hpart[t] = r;
        }
        __syncthreads();
        if (t < 64) {
            float v = updh[t] + sB2[t] + (hpart[t] + hpart[t + 64]);
            snew[t] = v;
            g_slots[b * 512 + s * 64 + t] = v;
            if (last) out[b * 512 + s * 64 + t] = v;
        }
        WAITG(0);
        __syncthreads();

        if (!last)
            prep_slot(b, s, t, snew, lns, qv, qtv, hpart, sLnsg, sLnsb,
                      (const float*)sWq, (const float*)sWk, sLng, sLnb);
        __syncthreads();
    }
}

// ---------------------------------------------------------------------------
extern "C" void kernel_launch(void* const* d_in, const int* in_sizes, int n_in,
                              void* d_out, int out_size)
{
    const float* x     = (const float*)d_in[0];
    const float* noise = (const float*)d_in[1];
    const float* mu    = (const float*)d_in[2];
    const float* lsig  = (const float*)d_in[3];
    const float* lng   = (const float*)d_in[4];
    const float* lnb   = (const float*)d_in[5];
    const float* lnsg  = (const float*)d_in[6];
    const float* lnsb  = (const float*)d_in[7];
    const float* lnmg  = (const float*)d_in[8];
    const float* lnmb  = (const float*)d_in[9];
    const float* Wq    = (const float*)d_in[10];
    const float* Wk    = (const float*)d_in[11];
    const float* Wv    = (const float*)d_in[12];
    const float* W_ih  = (const float*)d_in[13];
    const float* W_hh  = (const float*)d_in[14];
    const float* b_ih  = (const float*)d_in[15];
    const float* b_hh  = (const float*)d_in[16];
    const float* W1    = (const float*)d_in[17];
    const float* b1    = (const float*)d_in[18];
    const float* W2    = (const float*)d_in[19];
    const float* b2    = (const float*)d_in[20];
    float* out = (float*)d_out;

    cudaFuncSetAttribute(k_pass, cudaFuncAttributeMaxDynamicSharedMemorySize, SMEM_BYTES);
    cudaFuncSetAttribute(k_update, cudaFuncAttributeMaxDynamicSharedMemorySize, UPD_SMEM);

    k_init<<<BB * SS, 128>>>(noise, mu, lsig, lnsg, lnsb, Wq, Wk, lng, lnb);

    for (int it = 0; it < 3; ++it) {
        k_pass<<<dim3(NBLKX, BB), PASS_THREADS, SMEM_BYTES>>>((const float4*)x);
        k_update<<<128, 128, UPD_SMEM>>>(lng, lnb, lnsg, lnsb, lnmg, lnmb,
                                         Wq, Wk, Wv, W_ih, W_hh, b_ih, b_hh,
                                         W1, b1, W2, b2, out, it == 2);
    }
}

// round 13
// speedup vs baseline: 1.1545x; 1.0371x over previous
#include <cuda_runtime.h>

// ---------------------------------------------------------------------------
// SlotAttention fused. B=32, N=16384, S=8, D=64, H=128, ITERS=3.
// k_pass: per-warp cp.async ring-2, PAIRED phase-1 (wts broadcast shared by
//         both ring buffers), folded-LN logits + softmax + rank-1 accum,
//         f32x2 FMAs (round-12 winner, 40.4us).
// k_update: 128 blocks x 256 threads; all weights staged to smem via cp.async;
//         the two (b,s) pairs run CONCURRENTLY in half-blocks (warps 0-3 and
//         4-7) sharing the staged weights -> serial phase chain runs once.
// ---------------------------------------------------------------------------

#define BB 32
#define NN 16384
#define SS 8
#define DD 64
#define HH 128
#define NBLKX 32                 // pass blocks per batch (512 rows each)
#define PREC 528                 // floats per record: 512 Pacc + 8 Sg + 8 Sb
#define PASS_THREADS 128
// k_pass smem: xs 4096f4 + as4 512f4 + wts 128f4 + tail 80f = 76096 -> 76160
#define SMEM_BYTES 76160
#define ACTF 1344                // floats per half-block activation region
#define UPD_SMEM ((13552 + 2 * (ACTF / 4)) * 16)   // 227584 bytes

typedef unsigned long long ull;

__device__ float  g_slots[BB * SS * DD];
__device__ float4 g_wts4[BB * 128];          // [b][k=0..15][s=0..7]
__device__ float  g_c0[BB][SS];
__device__ float  g_c1[BB][SS];
__device__ float4 g_part4[(size_t)BB * NBLKX * 132];

#define F2FMA(d, a, b) asm("fma.rn.f32x2 %0, %1, %2, %0;" : "+l"(d) : "l"(a), "l"(b))
#define F2ADD(d, a, b) asm("add.rn.f32x2 %0, %1, %2;" : "=l"(d) : "l"(a), "l"(b))
#define F2PACK(v, lo, hi) asm("mov.b64 %0, {%1, %2};" : "=l"(v) : "f"(lo), "f"(hi))
#define F2UNPK(lo, hi, v) asm("mov.b64 {%0, %1}, %2;" : "=f"(lo), "=f"(hi) : "l"(v))

#define CPA(dst, src) asm volatile("cp.async.cg.shared.global [%0], [%1], 16;" \
                                   :: "r"(dst), "l"(src))
#define CPCOMMIT() asm volatile("cp.async.commit_group;")
#define WAITG(n) asm volatile("cp.async.wait_group " #n ";" ::: "memory")

__device__ __forceinline__ float sigm(float x) { return 1.f / (1.f + __expf(-x)); }

__global__ void k_nop() {}   // aligns ncu -s 5 onto k_update#2

__device__ __forceinline__ float dot16x4(const float4* a, const float4* w, float bias) {
    float a0 = 0.f, a1 = 0.f, a2 = 0.f, a3 = 0.f;
#pragma unroll
    for (int e = 0; e < 4; ++e) {
        float4 x0 = a[e],      w0 = w[e];
        float4 x1 = a[e + 4],  w1 = w[e + 4];
        float4 x2 = a[e + 8],  w2 = w[e + 8];
        float4 x3 = a[e + 12], w3 = w[e + 12];
        a0 = fmaf(x0.x, w0.x, fmaf(x0.y, w0.y, fmaf(x0.z, w0.z, fmaf(x0.w, w0.w, a0))));
        a1 = fmaf(x1.x, w1.x, fmaf(x1.y, w1.y, fmaf(x1.z, w1.z, fmaf(x1.w, w1.w, a1))));
        a2 = fmaf(x2.x, w2.x, fmaf(x2.y, w2.y, fmaf(x2.z, w2.z, fmaf(x2.w, w2.w, a2))));
        a3 = fmaf(x3.x, w3.x, fmaf(x3.y, w3.y, fmaf(x3.z, w3.z, fmaf(x3.w, w3.w, a3))));
    }
    return bias + ((a0 + a1) + (a2 + a3));
}
__device__ __forceinline__ float dot8x4(const float4* a, const float4* w) {
    float a0 = 0.f, a1 = 0.f;
#pragma unroll
    for (int e = 0; e < 4; ++e) {
        float4 x0 = a[e],     w0 = w[e];
        float4 x1 = a[e + 4], w1 = w[e + 4];
        a0 = fmaf(x0.x, w0.x, fmaf(x0.y, w0.y, fmaf(x0.z, w0.z, fmaf(x0.w, w0.w, a0))));
        a1 = fmaf(x1.x, w1.x, fmaf(x1.y, w1.y, fmaf(x1.z, w1.z, fmaf(x1.w, w1.w, a1))));
    }
    return a0 + a1;
}

__device__ __forceinline__ void ln64_warp(const float* in, float* out,
                                          const float* g,
                                          const float* bt, int t) {
    if (t < 32) {
        float v0 = in[t], v1 = in[t + 32];
        float sum = v0 + v1;
        float sq  = fmaf(v0, v0, v1 * v1);
#pragma unroll
        for (int off = 16; off; off >>= 1) {
            sum += __shfl_xor_sync(0xffffffffu, sum, off);
            sq  += __shfl_xor_sync(0xffffffffu, sq,  off);
        }
        float m    = sum * (1.f / 64.f);
        float istd = rsqrtf(fmaf(sq, 1.f / 64.f, -m * m) + 1e-5f);
        out[t]      = fmaf((v0 - m) * istd, g[t],      bt[t]);
        out[t + 32] = fmaf((v1 - m) * istd, g[t + 32], bt[t + 32]);
    }
}

// ---------------------------------------------------------------------------
// per-(b,s) prep. Uniform control flow across the block (safe __syncthreads
// even when called by two half-blocks with different b).
// ---------------------------------------------------------------------------
__device__ __forceinline__ void prep_slot(
    int b, int s, int t,
    const float* snew, float* lns, float* qv, float* qtv, float* hpart,
    const float* lnsg, const float* lnsb,
    const float* Wq,   const float* Wk,
    const float* lng,  const float* lnb)
{
    ln64_warp(snew, lns, lnsg, lnsb, t);
    __syncthreads();
    {
        int dd = t & 63, h = t >> 6;
        const float4* wr = (const float4*)(Wq + dd * 64) + h * 8;
        const float4* lv = (const float4*)lns + h * 8;
        hpart[t] = dot8x4(lv, wr);
    }
    __syncthreads();
    if (t < 64) qv[t] = (hpart[t] + hpart[t + 64]) * 0.125f;
    __syncthreads();
    {
        int e = t & 63, h = t >> 6;
        float acc = 0.f;
        const float* wk = Wk + (h * 32) * 64 + e;
#pragma unroll 8
        for (int dd = 0; dd < 32; ++dd) acc = fmaf(qv[h * 32 + dd], wk[dd * 64], acc);
        hpart[t] = acc;
    }
    __syncthreads();
    if (t < 64) qtv[t] = hpart[t] + hpart[t + 64];
    __syncthreads();
    if (t < 64) {
        int k = t >> 2, j = t & 3;
        reinterpret_cast<float*>(g_wts4 + b * 128)[(k * 8 + s) * 4 + j] = lng[t] * qtv[t];
    }
    if (t < 32) {
        float p1 = fmaf(lng[t + 32], qtv[t + 32], lng[t] * qtv[t]);
        float p0 = fmaf(lnb[t + 32], qtv[t + 32], lnb[t] * qtv[t]);
#pragma unroll
        for (int off = 16; off; off >>= 1) {
            p1 += __shfl_xor_sync(0xffffffffu, p1, off);
            p0 += __shfl_xor_sync(0xffffffffu, p0, off);
        }
        if (t == 0) { g_c1[b][s] = p1; g_c0[b][s] = p0; }
    }
}

// ---------------------------------------------------------------------------
__global__ void __launch_bounds__(128) k_init(
    const float* __restrict__ noise, const float* __restrict__ mu,
    const float* __restrict__ lsig,
    const float* __restrict__ lnsg, const float* __restrict__ lnsb,
    const float* __restrict__ Wq,   const float* __restrict__ Wk,
    const float* __restrict__ lng,  const float* __restrict__ lnb)
{
    __shared__ __align__(16) float snew[64], lns[64], qv[64], qtv[64], hpart[128];
    int bs = blockIdx.x, b = bs >> 3, s = bs & 7, t = threadIdx.x;
    if (t < 64) {
        int idx = s * 64 + t;
        float v = fmaf(__expf(lsig[idx]), noise[b * 512 + idx], mu[idx]);
        snew[t] = v;
        g_slots[b * 512 + idx] = v;
    }
    __syncthreads();
    prep_slot(b, s, t, snew, lns, qv, qtv, hpart, lnsg, lnsb, Wq, Wk, lng, lnb);
}

// ---------------------------------------------------------------------------
__device__ __forceinline__ void stage_tile(const float4* __restrict__ gsrc,
                                           unsigned sdst, int l)
{
#pragma unroll
    for (int j = 0; j < 16; ++j) {
        int flat = j * 32 + l;
        int row = flat >> 4, k = flat & 15;
        unsigned dst = sdst + (unsigned)((row * 16 + (k ^ (row & 15))) * 16);
        CPA(dst, gsrc + flat);
    }
    CPCOMMIT();
}

// phase-1 epilogue: stats -> softmax -> alphas; accumulates Sg/Sb partials
__device__ __forceinline__ void p1_epilogue(
    const ull* d2, ull sum2, ull sqa, ull sqb,
    const float* c0r, const float* c1r,
    float* gacc, float* bacc, float4* dst, int l)
{
    float slo, shi; F2UNPK(slo, shi, sum2);
    float sum = slo + shi;
    float qa0, qa1, qb0, qb1;
    F2UNPK(qa0, qa1, sqa); F2UNPK(qb0, qb1, sqb);
    float sq = (qa0 + qa1) + (qb0 + qb1);
    float m    = sum * (1.f / 64.f);
    float istd = rsqrtf(fmaf(sq, 1.f / 64.f, -m * m) + 1e-5f);
    float lo[8], mx = -3.4e38f;
#pragma unroll
    for (int s = 0; s < 8; ++s) {
        float dlo, dhi; F2UNPK(dlo, dhi, d2[s]);
        float d = dlo + dhi;
        lo[s] = fmaf(istd, fmaf(-m, c1r[s], d), c0r[s]);
        mx = fmaxf(mx, lo[s]);
    }
    float pr[8], ps = 0.f;
#pragma unroll
    for (int s = 0; s < 8; ++s) { pr[s] = __expf(lo[s] - mx); ps += pr[s]; }
    float rc  = 1.f / ps;
    float tmi = m * istd;
    float al[8];
#pragma unroll
    for (int s = 0; s < 8; ++s) {
        float a = fmaf(pr[s], rc, 1e-8f);   // softmax + EPS
        gacc[s] += a;
        bacc[s] = fmaf(a, tmi, bacc[s]);
        al[s]   = a * istd;
    }
    dst[l * 2 + 0] = make_float4(al[0], al[1], al[2], al[3]);
    dst[l * 2 + 1] = make_float4(al[4], al[5], al[6], al[7]);
}

// phase-2 rank-1 accumulation over one 32-row tile
__device__ __forceinline__ void p2_accum(
    const ulonglong2* xs2w, const float4* as4t, ull* p2, int g2, int e4)
{
#pragma unroll 4
    for (int r = 0; r < 32; ++r) {
        float4 av = as4t[r * 2 + g2];
        ulonglong2 xq = xs2w[r * 16 + (e4 ^ (r & 15))];
        ull a0, a1, a2, a3;
        F2PACK(a0, av.x, av.x); F2PACK(a1, av.y, av.y);
        F2PACK(a2, av.z, av.z); F2PACK(a3, av.w, av.w);
        F2FMA(p2[0], xq.x, a0); F2FMA(p2[1], xq.y, a0);
        F2FMA(p2[2], xq.x, a1); F2FMA(p2[3], xq.y, a1);
        F2FMA(p2[4], xq.x, a2); F2FMA(p2[5], xq.y, a2);
        F2FMA(p2[6], xq.x, a3); F2FMA(p2[7], xq.y, a3);
    }
}

// ---------------------------------------------------------------------------
// the big fused pass, paired phase-1 (round-12 winner).
// ---------------------------------------------------------------------------
__global__ void __launch_bounds__(PASS_THREADS, 3) k_pass(const float4* __restrict__ x4)
{
    extern __shared__ __align__(16) float4 smem[];
    float4* xs   = smem;
    float4* as4  = smem + 4096;
    float4* wts  = smem + 4608;
    float*  tail = (float*)(smem + 4736);   // 80 floats

    const int b = blockIdx.y;
    const int t = threadIdx.x;
    const int w = t >> 5, l = t & 31;

    unsigned smem_u32;
    { size_t a = __cvta_generic_to_shared(xs); smem_u32 = (unsigned)a; }
    const unsigned xs_base = smem_u32 + (unsigned)(w * 1024 * 16);

    const float4* gwarp = x4 + ((size_t)b * NN + (size_t)blockIdx.x * 512 + w * 128) * 16;
    stage_tile(gwarp,       xs_base,        l);   // t0 -> buf0
    stage_tile(gwarp + 512, xs_base + 8192, l);   // t1 -> buf1

    wts[t] = g_wts4[b * 128 + t];
    if (t < 8)  tail[t]     = g_c0[b][t];
    if (t >= 8 && t < 16) tail[t] = g_c1[b][t - 8];
    __syncthreads();

    float c0r[8], c1r[8], gacc[8], bacc[8];
    ull p2[8];
#pragma unroll
    for (int s = 0; s < 8; ++s) {
        c0r[s] = tail[s]; c1r[s] = tail[8 + s];
        gacc[s] = 0.f; bacc[s] = 0.f; p2[s] = 0ULL;
    }

    const ulonglong2* wt2 = reinterpret_cast<const ulonglong2*>(wts);
    float4* as4w = as4 + w * 128;          // 2 tiles x 64
    const int g2 = l >> 4, e4 = l & 15;
    const ulonglong2* xsA = reinterpret_cast<const ulonglong2*>(xs + w * 1024);
    const ulonglong2* xsB = reinterpret_cast<const ulonglong2*>(xs + w * 1024 + 512);

#pragma unroll
    for (int pr = 0; pr < 2; ++pr) {
        WAITG(0);
        __syncwarp();

        {
            ull dA[8], dB[8];
#pragma unroll
            for (int s = 0; s < 8; ++s) { dA[s] = 0ULL; dB[s] = 0ULL; }
            ull sumA = 0ULL, sumB = 0ULL, sqaA = 0ULL, sqaB = 0ULL, sqbA = 0ULL, sqbB = 0ULL;
            const int rb = l * 16, ro = l & 15;
#pragma unroll
            for (int k = 0; k < 16; ++k) {
                ulonglong2 vA = xsA[rb + (k ^ ro)];
                ulonglong2 vB = xsB[rb + (k ^ ro)];
                ull tv;
                F2ADD(tv, vA.x, vA.y); F2ADD(sumA, sumA, tv);
                F2ADD(tv, vB.x, vB.y); F2ADD(sumB, sumB, tv);
                F2FMA(sqaA, vA.x, vA.x); F2FMA(sqbA, vA.y, vA.y);
                F2FMA(sqaB, vB.x, vB.x); F2FMA(sqbB, vB.y, vB.y);
#pragma unroll
                for (int s = 0; s < 8; ++s) {
                    ulonglong2 wv = wt2[k * 8 + s];
                    F2FMA(dA[s], vA.x, wv.x); F2FMA(dA[s], vA.y, wv.y);
                    F2FMA(dB[s], vB.x, wv.x); F2FMA(dB[s], vB.y, wv.y);
                }
            }
            p1_epilogue(dA, sumA, sqaA, sqbA, c0r, c1r, gacc, bacc, as4w,      l);
            p1_epilogue(dB, sumB, sqaB, sqbB, c0r, c1r, gacc, bacc, as4w + 64, l);
        }
        __syncwarp();

        p2_accum(xsA, as4w, p2, g2, e4);
        if (pr == 0) stage_tile(gwarp + 2 * 512, xs_base, l);        // t2 -> buf0
        p2_accum(xsB, as4w + 64, p2, g2, e4);
        if (pr == 0) stage_tile(gwarp + 3 * 512, xs_base + 8192, l); // t3 -> buf1
        __syncwarp();
    }

#pragma unroll
    for (int s = 0; s < 8; ++s) {
        float gv = gacc[s], bv = bacc[s];
#pragma unroll
        for (int off = 16; off; off >>= 1) {
            gv += __shfl_xor_sync(0xffffffffu, gv, off);
            bv += __shfl_xor_sync(0xffffffffu, bv, off);
        }
        if (l == 0) { tail[16 + w * 8 + s] = gv; tail[48 + w * 8 + s] = bv; }
    }
    __syncthreads();

    float4* red4 = xs;
#pragma unroll
    for (int ss = 0; ss < 4; ++ss) {
        float x0, x1, x2, x3;
        F2UNPK(x0, x1, p2[2 * ss]);
        F2UNPK(x2, x3, p2[2 * ss + 1]);
        red4[w * 128 + (4 * g2 + ss) * 16 + e4] = make_float4(x0, x1, x2, x3);
    }
    __syncthreads();

    float4* gp4 = g_part4 + ((size_t)(b * NBLKX + blockIdx.x)) * 132;
    {
        float4 a = red4[t], bb2 = red4[128 + t], c = red4[256 + t], d = red4[384 + t];
        float4 o;
        o.x = ((a.x + bb2.x) + c.x) + d.x;
        o.y = ((a.y + bb2.y) + c.y) + d.y;
        o.z = ((a.z + bb2.z) + c.z) + d.z;
        o.w = ((a.w + bb2.w) + c.w) + d.w;
        gp4[t] = o;
    }
    if (t < 16) {
        const float* src = tail + 16 + (t >= 8 ? 32 : 0) + (t & 7);
        float v = ((src[0] + src[8]) + src[16]) + src[24];
        reinterpret_cast<float*>(gp4)[512 + (t >= 8 ? 8 : 0) + (t & 7)] = v;
    }
}

// ---------------------------------------------------------------------------
// slot update: 128 blocks x 256 threads; half-block hb handles (b0+16*hb, s).
// Both halves run the phase chain concurrently over shared staged weights.
// ---------------------------------------------------------------------------
__global__ void __launch_bounds__(256) k_update(
    const float* __restrict__ lng,  const float* __restrict__ lnb,
    const float* __restrict__ lnsg, const float* __restrict__ lnsb,
    const float* __restrict__ lnmg, const float* __restrict__ lnmb,
    const float* __restrict__ Wq,   const float* __restrict__ Wk,
    const float* __restrict__ Wv,
    const float* __restrict__ W_ih, const float* __restrict__ W_hh,
    const float* __restrict__ b_ih, const float* __restrict__ b_hh,
    const float* __restrict__ W1,   const float* __restrict__ b1,
    const float* __restrict__ W2,   const float* __restrict__ b2,
    float* __restrict__ out, int last)
{
    extern __shared__ __align__(16) float4 smu[];
    float4* sWv  = smu;
    float4* sWih = smu + 1024;
    float4* sWhh = smu + 4096;
    float4* sW1  = smu + 7168;
    float4* sW2  = smu + 9216;
    float4* sWq  = smu + 11264;
    float4* sWk  = smu + 12288;
    float*  sPar = (float*)(smu + 13312);

    float *sBih = sPar, *sBhh = sPar + 192, *sB1 = sPar + 384, *sB2 = sPar + 512;
    float *sLng = sPar + 576, *sLnb = sPar + 640, *sLnsg = sPar + 704;
    float *sLnsb = sPar + 768, *sLnmg = sPar + 832, *sLnmb = sPar + 896;

    const int bx = blockIdx.x, b0 = bx >> 3, s = bx & 7;
    const int t = threadIdx.x;
    const int hb = t >> 7, t2 = t & 127;
    const int b = b0 + 16 * hb;

    // per-half activation region
    float* act = (float*)(smu + 13552) + hb * ACTF;
    float *P = act, *Uv = act + 64, *upds = act + 128, *slp = act + 192;
    float *updh = act + 256, *mln = act + 320, *snew = act + 384;
    float *lns = act + 448, *qv = act + 512, *qtv = act + 576;
    float *gi = act + 640, *gh = act + 832, *hhs = act + 1024, *hpart = act + 1152;
    float4* pg4 = (float4*)(act + 640);   // aliases gi (consumed before D)
    float*  sred = act + 1280;            // 8
    float*  sS   = act + 1288;            // [0]=Sg [1]=Sb

    unsigned sb;
    { size_t a = __cvta_generic_to_shared(smu); sb = (unsigned)a; }
    const unsigned parU = sb + 13312u * 16u;

    // ---- G0: Wv + biases + ln params (all 256 threads) ----
    for (int i = t; i < 1024; i += 256) CPA(sb + i * 16, (const float4*)Wv + i);
    if (t < 48) CPA(parU + t * 16,          (const float4*)b_ih + t);
    if (t >= 48 && t < 96)  CPA(parU + t * 16, (const float4*)b_hh + (t - 48));
    if (t >= 96 && t < 128) CPA(parU + t * 16, (const float4*)b1 + (t - 96));
    if (t >= 128 && t < 144) CPA(parU + t * 16, (const float4*)b2 + (t - 128));
    if (t >= 144 && t < 160) CPA(parU + t * 16, (const float4*)lng + (t - 144));
    if (t >= 160 && t < 176) CPA(parU + t * 16, (const float4*)lnb + (t - 160));
    if (t >= 176 && t < 192) CPA(parU + t * 16, (const float4*)lnsg + (t - 176));
    if (t >= 192 && t < 208) CPA(parU + t * 16, (const float4*)lnsb + (t - 192));
    if (t >= 208 && t < 224) CPA(parU + t * 16, (const float4*)lnmg + (t - 208));
    if (t >= 224 && t < 240) CPA(parU + t * 16, (const float4*)lnmb + (t - 224));
    CPCOMMIT();
    // ---- G1: W_ih ----
    for (int i = t; i < 3072; i += 256) CPA(sb + (1024 + i) * 16, (const float4*)W_ih + i);
    CPCOMMIT();
    // ---- G2: W_hh ----
    for (int i = t; i < 3072; i += 256) CPA(sb + (4096 + i) * 16, (const float4*)W_hh + i);
    CPCOMMIT();

    // ---- A: coalesced fixed-order reduce of 32 records for this (b,s) ----
    {
        const float4* pb4 = g_part4 + (size_t)b * NBLKX * 132;
        if (t2 < 64) {
            int e4 = t2 & 15, grp = t2 >> 4;
            const float4* src = pb4 + (size_t)grp * 8 * 132 + s * 16 + e4;
            float4 acc = make_float4(0.f, 0.f, 0.f, 0.f);
#pragma unroll
            for (int j = 0; j < 8; ++j) {
                float4 v = src[(size_t)j * 132];
                acc.x += v.x; acc.y += v.y; acc.z += v.z; acc.w += v.w;
            }
            pg4[grp * 16 + e4] = acc;
        } else if (t2 < 72) {
            int which = (t2 - 64) >> 2;
            int grp = (t2 - 64) & 3;
            const float* src = reinterpret_cast<const float*>(pb4)
                             + (size_t)grp * 8 * PREC + 512 + which * 8 + s;
            float acc = 0.f;
#pragma unroll
            for (int j = 0; j < 8; ++j) acc += src[(size_t)j * PREC];
            sred[t2 - 64] = acc;
        }
        if (t2 >= 64) slp[t2 - 64] = g_slots[b * 512 + s * 64 + (t2 - 64)];
    }

    // ---- G3..G6 (overlap with phase-A latency) ----
    for (int i = t; i < 2048; i += 256) CPA(sb + (7168 + i) * 16, (const float4*)W1 + i);
    CPCOMMIT();
    for (int i = t; i < 2048; i += 256) CPA(sb + (9216 + i) * 16, (const float4*)W2 + i);
    CPCOMMIT();
    for (int i = t; i < 1024; i += 256) CPA(sb + (11264 + i) * 16, (const float4*)Wq + i);
    CPCOMMIT();
    for (int i = t; i < 1024; i += 256) CPA(sb + (12288 + i) * 16, (const float4*)Wk + i);
    CPCOMMIT();

    WAITG(6);            // G0 (Wv + params) complete
    __syncthreads();
    if (t2 < 16) {
        float4 a = pg4[t2], bg = pg4[16 + t2], c = pg4[32 + t2], d = pg4[48 + t2];
        float4 o;
        o.x = ((a.x + bg.x) + c.x) + d.x;
        o.y = ((a.y + bg.y) + c.y) + d.y;
        o.z = ((a.z + bg.z) + c.z) + d.z;
        o.w = ((a.w + bg.w) + c.w) + d.w;
        reinterpret_cast<float4*>(P)[t2] = o;
    }
    if (t2 == 0) sS[0] = ((sred[0] + sred[1]) + sred[2]) + sred[3];
    if (t2 == 1) sS[1] = ((sred[4] + sred[5]) + sred[6]) + sred[7];
    __syncthreads();

    // ---- B: U[e] = (g*(P - Sb) + b*Sg)/Sg ----
    if (t2 < 64) Uv[t2] = fmaf(sLng[t2], P[t2] - sS[1], sLnb[t2] * sS[0]) / sS[0];
    __syncthreads();

    // ---- C: upds = U @ Wv^T (half-split) ----
    {
        int dd = t2 & 63, h = t2 >> 6;
        float r = dot8x4((const float4*)Uv + h * 8, sWv + dd * 16 + h * 8);
        __syncthreads();          // hpart WAR (uniform)
        hpart[t2] = r;
    }
    __syncthreads();
    if (t2 < 64) upds[t2] = hpart[t2] + hpart[t2 + 64];
    WAITG(4);            // G1,G2 (W_ih, W_hh) complete
    __syncthreads();

    // ---- D: GRU pre-activations ----
#pragma unroll
    for (int k = 0; k < 3; ++k) {
        int id = t2 + 128 * k;
        if (id < 192) {
            gi[id] = dot16x4((const float4*)upds, sWih + id * 16, sBih[id]);
        } else {
            int j = id - 192;
            gh[j] = dot16x4((const float4*)slp, sWhh + j * 16, sBhh[j]);
        }
    }
    __syncthreads();

    // ---- E: gates ----
    if (t2 < 64) {
        float r = sigm(gi[t2]      + gh[t2]);
        float z = sigm(gi[64 + t2] + gh[64 + t2]);
        float n = tanhf(fmaf(r, gh[128 + t2], gi[128 + t2]));
        updh[t2] = fmaf(z, slp[t2] - n, n);
    }
    __syncthreads();

    // ---- F: LN(updh) ----
    ln64_warp(updh, mln, sLnmg, sLnmb, t2);
    WAITG(3);            // W1 complete
    __syncthreads();

    // ---- G: hidden = relu(mln @ W1^T + b1) ----
    hhs[t2] = fmaxf(dot16x4((const float4*)mln, sW1 + t2 * 16, sB1[t2]), 0.f);
    WAITG(2);            // W2 complete
    __syncthreads();

    // ---- H: snew = updh + hh @ W2^T + b2 ----
    {
        int dd = t2 & 63, h = t2 >> 6;
        float r = dot16x4((const float4*)hhs + h * 16, sW2 + dd * 32 + h * 16, 0.f);
        __syncthreads();
        hpart[t2] = r;
    }
    __syncthreads();
    if (t2 < 64) {
        float v = updh[t2] + sB2[t2] + (hpart[t2] + hpart[t2 + 64]);
        snew[t2] = v;
        g_slots[b * 512 + s * 64 + t2] = v;
        if (last) out[b * 512 + s * 64 + t2] = v;
    }
    WAITG(0);            // Wq, Wk complete
    __syncthreads();

    if (!last)
        prep_slot(b, s, t2, snew, lns, qv, qtv, hpart, sLnsg, sLnsb,
                  (const float*)sWq, (const float*)sWk, sLng, sLnb);
}

// ---------------------------------------------------------------------------
extern "C" void kernel_launch(void* const* d_in, const int* in_sizes, int n_in,
                              void* d_out, int out_size)
{
    const float* x     = (const float*)d_in[0];
    const float* noise = (const float*)d_in[1];
    const float* mu    = (const float*)d_in[2];
    const float* lsig  = (const float*)d_in[3];
    const float* lng   = (const float*)d_in[4];
    const float* lnb   = (const float*)d_in[5];
    const float* lnsg  = (const float*)d_in[6];
    const float* lnsb  = (const float*)d_in[7];
    const float* lnmg  = (const float*)d_in[8];
    const float* lnmb  = (const float*)d_in[9];
    const float* Wq    = (const float*)d_in[10];
    const float* Wk    = (const float*)d_in[11];
    const float* Wv    = (const float*)d_in[12];
    const float* W_ih  = (const float*)d_in[13];
    const float* W_hh  = (const float*)d_in[14];
    const float* b_ih  = (const float*)d_in[15];
    const float* b_hh  = (const float*)d_in[16];
    const float* W1    = (const float*)d_in[17];
    const float* b1    = (const float*)d_in[18];
    const float* W2    = (const float*)d_in[19];
    const float* b2    = (const float*)d_in[20];
    float* out = (float*)d_out;

    cudaFuncSetAttribute(k_pass, cudaFuncAttributeMaxDynamicSharedMemorySize, SMEM_BYTES);
    cudaFuncSetAttribute(k_update, cudaFuncAttributeMaxDynamicSharedMemorySize, UPD_SMEM);

    k_nop<<<1, 32>>>();   // aligns ncu -s 5 onto k_update#2
    k_init<<<BB * SS, 128>>>(noise, mu, lsig, lnsg, lnsb, Wq, Wk, lng, lnb);

    for (int it = 0; it < 3; ++it) {
        k_pass<<<dim3(NBLKX, BB), PASS_THREADS, SMEM_BYTES>>>((const float4*)x);
        k_update<<<128, 256, UPD_SMEM>>>(lng, lnb, lnsg, lnsb, lnmg, lnmb,
                                         Wq, Wk, Wv, W_ih, W_hh, b_ih, b_hh,
                                         W1, b1, W2, b2, out, it == 2);
    }
}